// round 7
// baseline (speedup 1.0000x reference)
#include <cuda_runtime.h>
#include <cuda_bf16.h>
#include <math.h>
#include <cstdint>

#define HD 450
#define NTREE 32
#define NB 1024
#define NNODE (NB*NTREE)
#define NV 780

// ---------------- scratch (static device memory) ----------------
__device__ float g_pz [NV*HD];     // emb@Wz_top + bz   per vocab
__device__ float g_ph [NV*HD];     // emb@Wh_top + bh
__device__ float g_pr [NV*HD];     // emb@Wr + bU
__device__ float g_pgt[NV*HD];     // emb@Wg_top + bg
__device__ float g_mlf[NV*HD];     // leaf message per vocab
__device__ float g_rur[NV*HD];     // mlf @ Ur
__device__ float g_m  [NNODE*HD];  // message per upward edge
__device__ float g_rm [NNODE*HD];  // r*m
__device__ __nv_bfloat16 g_mh[NNODE*HD];   // m split hi (interior nodes)
__device__ __nv_bfloat16 g_ml[NNODE*HD];   // m split lo
__device__ __nv_bfloat16 g_wh[8*HD*HD];    // preconverted weights hi
__device__ __nv_bfloat16 g_wl[8*HD*HD];    // preconverted weights lo
// weight slots: 0 Wz_top, 1 Wz_bot, 2 Wh_top, 3 Wh_bot, 4 Wr, 5 Ur, 6 Wg_top, 7 Wg_bot

// ================= mma.sync helpers =================
constexpr int BM = 128, BN = 64, BK = 32;
constexpr int NCHK = (HD + BK - 1) / BK;   // 15
constexpr int ASTR = 40;
constexpr int BSTR = 72;
constexpr int SMEM_ZHM = (4 * BM * ASTR + 4 * BK * BSTR) * 2;  // 59392 bytes

__device__ __forceinline__ void ldm_x4(uint32_t* r, uint32_t addr) {
    asm volatile("ldmatrix.sync.aligned.m8n8.x4.shared.b16 {%0,%1,%2,%3}, [%4];"
                 : "=r"(r[0]), "=r"(r[1]), "=r"(r[2]), "=r"(r[3]) : "r"(addr));
}
__device__ __forceinline__ void ldm_x2t(uint32_t* r, uint32_t addr) {
    asm volatile("ldmatrix.sync.aligned.m8n8.x2.trans.shared.b16 {%0,%1}, [%2];"
                 : "=r"(r[0]), "=r"(r[1]) : "r"(addr));
}
__device__ __forceinline__ void mma_bf16(float* c, const uint32_t* a, const uint32_t* b) {
    asm volatile("mma.sync.aligned.m16n8k16.row.col.f32.bf16.bf16.f32 "
                 "{%0,%1,%2,%3}, {%4,%5,%6,%7}, {%8,%9}, {%0,%1,%2,%3};"
                 : "+f"(c[0]), "+f"(c[1]), "+f"(c[2]), "+f"(c[3])
                 : "r"(a[0]), "r"(a[1]), "r"(a[2]), "r"(a[3]), "r"(b[0]), "r"(b[1]));
}
__device__ __forceinline__ void split2(float2 v, uint32_t& hi, uint32_t& lo) {
    __nv_bfloat162 h = __floats2bfloat162_rn(v.x, v.y);
    __nv_bfloat162 l = __floats2bfloat162_rn(v.x - __bfloat162float(h.x),
                                             v.y - __bfloat162float(h.y));
    hi = *(uint32_t*)&h;
    lo = *(uint32_t*)&l;
}

// ================= single-source GEMM body =================
// C[M x 450] = gatherA[M x 450] @ W[450 x 450] (fp32 via bf16x3 split)
// AM: 0 dense fp32 A; 1 fp32 child-sum; 3 preconverted bf16 hi/lo node read
// EPI: 0 plain; 1 +bias; 3 rm=sig(pr[wp]+acc)*msrc; 4 relu(ptab[w0]+acc)
template<int AM, int EPI>
__device__ __forceinline__ void gemm_body(
    const float* __restrict__ A,
    const __nv_bfloat16* __restrict__ Amh, const __nv_bfloat16* __restrict__ Aml,
    const __nv_bfloat16* __restrict__ Bhg, const __nv_bfloat16* __restrict__ Blg,
    const float* __restrict__ bias, float* __restrict__ C,
    int M, int lo, int lg,
    const int* __restrict__ wid, const float* __restrict__ ptab,
    const float* __restrict__ pr, const float* __restrict__ msrc)
{
    __shared__ __align__(16) __nv_bfloat16 Ah[BM * ASTR], Al[BM * ASTR];
    __shared__ __align__(16) __nv_bfloat16 Bh[BK * BSTR], Bl[BK * BSTR];

    const int tid = threadIdx.x;
    const int lane = tid & 31, wrp = tid >> 5;
    const int wm = wrp & 3, wn = wrp >> 2;
    const int n0 = blockIdx.x * BN, m0 = blockIdx.y * BM;

    const uint32_t sAh = (uint32_t)__cvta_generic_to_shared(Ah);
    const uint32_t sAl = (uint32_t)__cvta_generic_to_shared(Al);
    const uint32_t sBh = (uint32_t)__cvta_generic_to_shared(Bh);
    const uint32_t sBl = (uint32_t)__cvta_generic_to_shared(Bl);

    float acc[2][4][4] = {};
    float2 av[8];
    uint32_t avh[8], avl[8], bvh[4], bvl[4];

    const int q = lane >> 3, r8 = lane & 7;
    const int arow_off = (q & 1) * 8 + r8;
    const int acol_off = (q >> 1) * 8;
    const int l16 = lane & 15;
    const int bk_off = (l16 >> 3) * 8 + (l16 & 7);

    auto loadA = [&](int c) {
#pragma unroll
        for (int i = 0; i < 8; i++) {
            int idx = tid + i * 256;
            int row = idx >> 4, col = (idx & 15) * 2;
            int k = c * BK + col, arow = m0 + row;
            if constexpr (AM == 3) {
                uint32_t h = 0, l = 0;
                if (arow < M && k < HD) {
                    int t = arow >> lg, ci = lo + (arow & ((1 << lg) - 1));
                    int g = (t * NTREE + ci) * HD + k;
                    h = *(const uint32_t*)&Amh[g];
                    l = *(const uint32_t*)&Aml[g];
                }
                avh[i] = h; avl[i] = l;
            } else {
                float2 v = make_float2(0.f, 0.f);
                if (arow < M && k < HD) {
                    if constexpr (AM == 0) {
                        v = *(const float2*)&A[arow * HD + k];
                    } else {   // AM == 1 child-sum
                        int t = arow >> lg, ci = lo + (arow & ((1 << lg) - 1));
                        int c1 = 2 * ci + 1;
                        const float* p1 = &A[(t * NTREE + c1) * HD + k];
                        v = *(const float2*)p1;
                        if (c1 + 1 < NTREE) {
                            float2 u = *(const float2*)(p1 + HD);
                            v.x += u.x; v.y += u.y;
                        }
                    }
                }
                av[i] = v;
            }
        }
    };
    auto loadB = [&](int c) {
#pragma unroll
        for (int i = 0; i < 4; i++) {
            int idx = tid + i * 256;
            int kk = idx >> 5, col = (idx & 31) * 2;
            int k = c * BK + kk, j = n0 + col;
            uint32_t h = 0, l = 0;
            if (k < HD && j < HD) {
                h = *(const uint32_t*)&Bhg[k * HD + j];
                l = *(const uint32_t*)&Blg[k * HD + j];
            }
            bvh[i] = h; bvl[i] = l;
        }
    };
    auto storeAB = [&]() {
#pragma unroll
        for (int i = 0; i < 8; i++) {
            int idx = tid + i * 256;
            int row = idx >> 4, col = (idx & 15) * 2;
            uint32_t hp, lp;
            if constexpr (AM == 3) { hp = avh[i]; lp = avl[i]; }
            else split2(av[i], hp, lp);
            *(uint32_t*)&Ah[row * ASTR + col] = hp;
            *(uint32_t*)&Al[row * ASTR + col] = lp;
        }
#pragma unroll
        for (int i = 0; i < 4; i++) {
            int idx = tid + i * 256;
            int kk = idx >> 5, col = (idx & 31) * 2;
            *(uint32_t*)&Bh[kk * BSTR + col] = bvh[i];
            *(uint32_t*)&Bl[kk * BSTR + col] = bvl[i];
        }
    };

    loadA(0); loadB(0);
    for (int c = 0; c < NCHK; c++) {
        __syncthreads();
        storeAB();
        __syncthreads();
        if (c + 1 < NCHK) { loadA(c + 1); loadB(c + 1); }   // overlap with MMA below
#pragma unroll
        for (int ks = 0; ks < 2; ks++) {
            uint32_t ah[2][4], al[2][4], bh[4][2], bl[4][2];
#pragma unroll
            for (int mf = 0; mf < 2; mf++) {
                int row = wm * 32 + mf * 16 + arow_off;
                int col = ks * 16 + acol_off;
                uint32_t off = (uint32_t)(row * ASTR + col) * 2;
                ldm_x4(ah[mf], sAh + off);
                ldm_x4(al[mf], sAl + off);
            }
#pragma unroll
            for (int nf = 0; nf < 4; nf++) {
                int krow = ks * 16 + bk_off;
                uint32_t off = (uint32_t)(krow * BSTR + wn * 32 + nf * 8) * 2;
                ldm_x2t(bh[nf], sBh + off);
                ldm_x2t(bl[nf], sBl + off);
            }
#pragma unroll
            for (int mf = 0; mf < 2; mf++)
#pragma unroll
                for (int nf = 0; nf < 4; nf++) {
                    mma_bf16(acc[mf][nf], ah[mf], bh[nf]);
                    mma_bf16(acc[mf][nf], ah[mf], bl[nf]);
                    mma_bf16(acc[mf][nf], al[mf], bh[nf]);
                }
        }
    }

    // ---- epilogue ----
    const int gr = lane >> 2, gc = (lane & 3) * 2;
#pragma unroll
    for (int mf = 0; mf < 2; mf++) {
#pragma unroll
        for (int h = 0; h < 2; h++) {
            int arow = m0 + wm * 32 + mf * 16 + h * 8 + gr;
            if (arow >= M) continue;
            int g = 0, wp = 0, w0 = 0;
            if constexpr (EPI == 3) {
                int t = arow >> lg, ci = lo + (arow & ((1 << lg) - 1));
                g  = t * NTREE + ci;
                wp = wid[t * NTREE + ((ci - 1) >> 1)];
            } else if constexpr (EPI == 4) {
                w0 = wid[arow * NTREE];
            }
#pragma unroll
            for (int nf = 0; nf < 4; nf++) {
                int j = n0 + wn * 32 + nf * 8 + gc;
                if (j >= HD) continue;
                float vx = acc[mf][nf][h * 2];
                float vy = acc[mf][nf][h * 2 + 1];
                if constexpr (EPI == 0) {
                    *(float2*)&C[arow * HD + j] = make_float2(vx, vy);
                } else if constexpr (EPI == 1) {
                    float2 b = *(const float2*)&bias[j];
                    *(float2*)&C[arow * HD + j] = make_float2(vx + b.x, vy + b.y);
                } else if constexpr (EPI == 3) {
                    float2 pv = *(const float2*)&pr[wp * HD + j];
                    float2 mv = *(const float2*)&msrc[g * HD + j];
                    float rx = 1.f / (1.f + expf(-(pv.x + vx)));
                    float ry = 1.f / (1.f + expf(-(pv.y + vy)));
                    *(float2*)&C[g * HD + j] = make_float2(rx * mv.x, ry * mv.y);
                } else { // EPI == 4
                    float2 pv = *(const float2*)&ptab[w0 * HD + j];
                    *(float2*)&C[arow * HD + j] =
                        make_float2(fmaxf(pv.x + vx, 0.f), fmaxf(pv.y + vy, 0.f));
                }
            }
        }
    }
}

// ================= fused zh + m_new kernel (dual accumulators, dynamic smem) =================
__global__ __launch_bounds__(256) void tc_zhm(
    const float* __restrict__ m, const float* __restrict__ rm,
    const __nv_bfloat16* __restrict__ wzh, const __nv_bfloat16* __restrict__ wzl,
    const __nv_bfloat16* __restrict__ whh, const __nv_bfloat16* __restrict__ whl,
    const int* __restrict__ wid, const float* __restrict__ pz, const float* __restrict__ ph_,
    float* __restrict__ mout, __nv_bfloat16* __restrict__ mh, __nv_bfloat16* __restrict__ ml,
    int M, int lo, int lg)
{
    extern __shared__ __align__(16) __nv_bfloat16 dynsm[];
    __nv_bfloat16* AhP[2] = { dynsm,                dynsm + BM * ASTR     };
    __nv_bfloat16* AlP[2] = { dynsm + 2 * BM * ASTR, dynsm + 3 * BM * ASTR };
    __nv_bfloat16* base_b = dynsm + 4 * BM * ASTR;
    __nv_bfloat16* BhP[2] = { base_b,                base_b + BK * BSTR     };
    __nv_bfloat16* BlP[2] = { base_b + 2 * BK * BSTR, base_b + 3 * BK * BSTR };

    const int tid = threadIdx.x;
    const int lane = tid & 31, wrp = tid >> 5;
    const int wm = wrp & 3, wn = wrp >> 2;
    const int n0 = blockIdx.x * BN, m0 = blockIdx.y * BM;

    uint32_t sAh[2], sAl[2], sBh[2], sBl[2];
#pragma unroll
    for (int s = 0; s < 2; s++) {
        sAh[s] = (uint32_t)__cvta_generic_to_shared(AhP[s]);
        sAl[s] = (uint32_t)__cvta_generic_to_shared(AlP[s]);
        sBh[s] = (uint32_t)__cvta_generic_to_shared(BhP[s]);
        sBl[s] = (uint32_t)__cvta_generic_to_shared(BlP[s]);
    }
    const float* srcA[2] = {m, rm};
    const __nv_bfloat16* Bhp[2] = {wzh, whh};
    const __nv_bfloat16* Blp[2] = {wzl, whl};

    float acc[2][2][4][4] = {};
    float2 av[2][8];
    uint32_t bvh[2][4], bvl[2][4];

    const int q = lane >> 3, r8 = lane & 7;
    const int arow_off = (q & 1) * 8 + r8;
    const int acol_off = (q >> 1) * 8;
    const int l16 = lane & 15;
    const int bk_off = (l16 >> 3) * 8 + (l16 & 7);

    auto loadAB = [&](int c) {
#pragma unroll
        for (int i = 0; i < 8; i++) {
            int idx = tid + i * 256;
            int row = idx >> 4, col = (idx & 15) * 2;
            int k = c * BK + col, arow = m0 + row;
            float2 v0 = make_float2(0.f, 0.f), v1 = v0;
            if (arow < M && k < HD) {
                int t = arow >> lg, ci = lo + (arow & ((1 << lg) - 1));
                int c1 = 2 * ci + 1;
                int base = (t * NTREE + c1) * HD + k;
                v0 = *(const float2*)&srcA[0][base];
                v1 = *(const float2*)&srcA[1][base];
                if (c1 + 1 < NTREE) {
                    float2 u0 = *(const float2*)&srcA[0][base + HD];
                    float2 u1 = *(const float2*)&srcA[1][base + HD];
                    v0.x += u0.x; v0.y += u0.y;
                    v1.x += u1.x; v1.y += u1.y;
                }
            }
            av[0][i] = v0; av[1][i] = v1;
        }
#pragma unroll
        for (int s = 0; s < 2; s++)
#pragma unroll
            for (int i = 0; i < 4; i++) {
                int idx = tid + i * 256;
                int kk = idx >> 5, col = (idx & 31) * 2;
                int k = c * BK + kk, j = n0 + col;
                uint32_t h = 0, l = 0;
                if (k < HD && j < HD) {
                    h = *(const uint32_t*)&Bhp[s][k * HD + j];
                    l = *(const uint32_t*)&Blp[s][k * HD + j];
                }
                bvh[s][i] = h; bvl[s][i] = l;
            }
    };
    auto storeAB = [&]() {
#pragma unroll
        for (int s = 0; s < 2; s++) {
#pragma unroll
            for (int i = 0; i < 8; i++) {
                int idx = tid + i * 256;
                int row = idx >> 4, col = (idx & 15) * 2;
                uint32_t hp, lp;
                split2(av[s][i], hp, lp);
                *(uint32_t*)&AhP[s][row * ASTR + col] = hp;
                *(uint32_t*)&AlP[s][row * ASTR + col] = lp;
            }
#pragma unroll
            for (int i = 0; i < 4; i++) {
                int idx = tid + i * 256;
                int kk = idx >> 5, col = (idx & 31) * 2;
                *(uint32_t*)&BhP[s][kk * BSTR + col] = bvh[s][i];
                *(uint32_t*)&BlP[s][kk * BSTR + col] = bvl[s][i];
            }
        }
    };

    loadAB(0);
    for (int c = 0; c < NCHK; c++) {
        __syncthreads();
        storeAB();
        __syncthreads();
        if (c + 1 < NCHK) loadAB(c + 1);
#pragma unroll
        for (int s = 0; s < 2; s++) {
#pragma unroll
            for (int ks = 0; ks < 2; ks++) {
                uint32_t ah[2][4], al[2][4], bh[4][2], bl[4][2];
#pragma unroll
                for (int mf = 0; mf < 2; mf++) {
                    int row = wm * 32 + mf * 16 + arow_off;
                    int col = ks * 16 + acol_off;
                    uint32_t off = (uint32_t)(row * ASTR + col) * 2;
                    ldm_x4(ah[mf], sAh[s] + off);
                    ldm_x4(al[mf], sAl[s] + off);
                }
#pragma unroll
                for (int nf = 0; nf < 4; nf++) {
                    int krow = ks * 16 + bk_off;
                    uint32_t off = (uint32_t)(krow * BSTR + wn * 32 + nf * 8) * 2;
                    ldm_x2t(bh[nf], sBh[s] + off);
                    ldm_x2t(bl[nf], sBl[s] + off);
                }
#pragma unroll
                for (int mf = 0; mf < 2; mf++)
#pragma unroll
                    for (int nf = 0; nf < 4; nf++) {
                        mma_bf16(acc[s][mf][nf], ah[mf], bh[nf]);
                        mma_bf16(acc[s][mf][nf], ah[mf], bl[nf]);
                        mma_bf16(acc[s][mf][nf], al[mf], bh[nf]);
                    }
            }
        }
    }

    // ---- epilogue: m_new = (1-z)*s + z*tanh(...), plus bf16 hi/lo split ----
    const int gr = lane >> 2, gc = (lane & 3) * 2;
#pragma unroll
    for (int mf = 0; mf < 2; mf++) {
#pragma unroll
        for (int h = 0; h < 2; h++) {
            int arow = m0 + wm * 32 + mf * 16 + h * 8 + gr;
            if (arow >= M) continue;
            int t = arow >> lg, ci = lo + (arow & ((1 << lg) - 1));
            int g = t * NTREE + ci;
            int w = wid[g];
            int c1 = 2 * ci + 1;
#pragma unroll
            for (int nf = 0; nf < 4; nf++) {
                int j = n0 + wn * 32 + nf * 8 + gc;
                if (j >= HD) continue;
                float2 pzv = *(const float2*)&pz[w * HD + j];
                float2 phv = *(const float2*)&ph_[w * HD + j];
                float zx = 1.f / (1.f + expf(-(pzv.x + acc[0][mf][nf][h * 2])));
                float zy = 1.f / (1.f + expf(-(pzv.y + acc[0][mf][nf][h * 2 + 1])));
                float tx = tanhf(phv.x + acc[1][mf][nf][h * 2]);
                float ty = tanhf(phv.y + acc[1][mf][nf][h * 2 + 1]);
                float2 s = *(const float2*)&m[(t * NTREE + c1) * HD + j];
                if (c1 + 1 < NTREE) {
                    float2 s2 = *(const float2*)&m[(t * NTREE + c1 + 1) * HD + j];
                    s.x += s2.x; s.y += s2.y;
                }
                float2 o = make_float2((1.f - zx) * s.x + zx * tx,
                                       (1.f - zy) * s.y + zy * ty);
                *(float2*)&mout[g * HD + j] = o;
                uint32_t hp, lp;
                split2(o, hp, lp);
                *(uint32_t*)&mh[g * HD + j] = hp;
                *(uint32_t*)&ml[g * HD + j] = lp;
            }
        }
    }
}

// ================= wrappers for single-source GEMMs =================
__global__ __launch_bounds__(256) void tc_vocab(
    const float* emb, const __nv_bfloat16* wh, const __nv_bfloat16* wl,
    const float* bz, const float* bh_, const float* bU, const float* bg,
    float* pz, float* ph_, float* pr, float* pgt)
{
    const int SZ = HD * HD;
    const float* b; float* C; int slot;
    switch (blockIdx.z) {
        case 0:  slot = 0; b = bz;  C = pz;  break;
        case 1:  slot = 2; b = bh_; C = ph_; break;
        case 2:  slot = 4; b = bU;  C = pr;  break;
        default: slot = 6; b = bg;  C = pgt; break;
    }
    gemm_body<0, 1>(emb, nullptr, nullptr, wh + slot * SZ, wl + slot * SZ,
                    b, C, NV, 0, 0, nullptr, nullptr, nullptr, nullptr);
}

__global__ __launch_bounds__(256) void tc_rur(
    const float* mlf, const __nv_bfloat16* urh, const __nv_bfloat16* url, float* rur)
{
    gemm_body<0, 0>(mlf, nullptr, nullptr, urh, url, nullptr, rur,
                    NV, 0, 0, nullptr, nullptr, nullptr, nullptr);
}

__global__ __launch_bounds__(256) void tc_ur(
    const __nv_bfloat16* mhg, const __nv_bfloat16* mlg,
    const __nv_bfloat16* urh, const __nv_bfloat16* url,
    float* rm, int M, int lo, int lg,
    const int* wid, const float* pr, const float* msrc)
{
    gemm_body<3, 3>(nullptr, mhg, mlg, urh, url, nullptr, rm,
                    M, lo, lg, wid, nullptr, pr, msrc);
}

__global__ __launch_bounds__(256) void tc_fin(
    const float* m, const __nv_bfloat16* wgh, const __nv_bfloat16* wgl,
    float* out, const int* wid, const float* pgt)
{
    gemm_body<1, 4>(m, nullptr, nullptr, wgh, wgl, nullptr, out,
                    NB, 0, 0, wid, pgt, nullptr, nullptr);
}

// ================= elementwise / preconvert =================
__global__ void preconv_k(const float* __restrict__ Wz, const float* __restrict__ Wh,
                          const float* __restrict__ Wr, const float* __restrict__ Ur,
                          const float* __restrict__ Wg,
                          __nv_bfloat16* __restrict__ wh, __nv_bfloat16* __restrict__ wl)
{
    int idx = blockIdx.x * blockDim.x + threadIdx.x;
    const int SZ = HD * HD;
    if (idx >= 8 * SZ) return;
    int slot = idx / SZ, off = idx - slot * SZ;
    float v;
    switch (slot) {
        case 0:  v = Wz[off];      break;
        case 1:  v = Wz[SZ + off]; break;
        case 2:  v = Wh[off];      break;
        case 3:  v = Wh[SZ + off]; break;
        case 4:  v = Wr[off];      break;
        case 5:  v = Ur[off];      break;
        case 6:  v = Wg[off];      break;
        default: v = Wg[SZ + off]; break;
    }
    __nv_bfloat16 h = __float2bfloat16(v);
    wh[idx] = h;
    wl[idx] = __float2bfloat16(v - __bfloat162float(h));
}

__global__ void mleaf_k(const float* __restrict__ pz, const float* __restrict__ ph,
                        float* __restrict__ mlf)
{
    int idx = blockIdx.x * blockDim.x + threadIdx.x;
    if (idx >= NV * (HD / 2)) return;
    int j = idx * 2;
    float2 a = *(const float2*)&pz[j];
    float2 b = *(const float2*)&ph[j];
    float zx = 1.f / (1.f + expf(-a.x)), zy = 1.f / (1.f + expf(-a.y));
    *(float2*)&mlf[j] = make_float2(zx * tanhf(b.x), zy * tanhf(b.y));
}

__global__ void leaf2_k(const int* __restrict__ wid,
                        const float* __restrict__ mlf, const float* __restrict__ rur,
                        const float* __restrict__ pr,
                        float* __restrict__ m, float* __restrict__ rm)
{
    int idx = blockIdx.x * blockDim.x + threadIdx.x;
    const int TOT = NB * 16 * (HD / 2);
    if (idx >= TOT) return;
    int a = idx / (HD / 2);
    int j = (idx - a * (HD / 2)) * 2;
    int t = a >> 4, ci = 16 + (a & 15);
    int g = t * NTREE + ci;
    int w = wid[g];
    int wp = wid[t * NTREE + ((ci - 1) >> 1)];
    float2 mv = *(const float2*)&mlf[w * HD + j];
    float2 ru = *(const float2*)&rur[w * HD + j];
    float2 pv = *(const float2*)&pr[wp * HD + j];
    float rx = 1.f / (1.f + expf(-(pv.x + ru.x)));
    float ry = 1.f / (1.f + expf(-(pv.y + ru.y)));
    *(float2*)&m[g * HD + j]  = mv;
    *(float2*)&rm[g * HD + j] = make_float2(rx * mv.x, ry * mv.y);
}

// ================= launch =================
extern "C" void kernel_launch(void* const* d_in, const int* in_sizes, int n_in,
                              void* d_out, int out_size)
{
    const int*   wid = (const int*)  d_in[0];
    const float* emb = (const float*)d_in[1];
    const float* Wz  = (const float*)d_in[2];
    const float* bz  = (const float*)d_in[3];
    const float* Wr  = (const float*)d_in[4];
    const float* Ur  = (const float*)d_in[5];
    const float* bU  = (const float*)d_in[6];
    const float* Wh  = (const float*)d_in[7];
    const float* bh  = (const float*)d_in[8];
    const float* Wg  = (const float*)d_in[9];
    const float* bg  = (const float*)d_in[10];
    float* out = (float*)d_out;

    float *pz, *ph, *pr, *pgt, *mlf, *rur, *m, *rm;
    __nv_bfloat16 *mh, *ml, *wh, *wl;
    cudaGetSymbolAddress((void**)&pz,  g_pz);
    cudaGetSymbolAddress((void**)&ph,  g_ph);
    cudaGetSymbolAddress((void**)&pr,  g_pr);
    cudaGetSymbolAddress((void**)&pgt, g_pgt);
    cudaGetSymbolAddress((void**)&mlf, g_mlf);
    cudaGetSymbolAddress((void**)&rur, g_rur);
    cudaGetSymbolAddress((void**)&m,   g_m);
    cudaGetSymbolAddress((void**)&rm,  g_rm);
    cudaGetSymbolAddress((void**)&mh,  g_mh);
    cudaGetSymbolAddress((void**)&ml,  g_ml);
    cudaGetSymbolAddress((void**)&wh,  g_wh);
    cudaGetSymbolAddress((void**)&wl,  g_wl);

    cudaFuncSetAttribute(tc_zhm, cudaFuncAttributeMaxDynamicSharedMemorySize, SMEM_ZHM);

    const int SZ = HD * HD;
    const int NX = (HD + BN - 1) / BN;   // 8
    auto yb = [](int M) { return (M + BM - 1) / BM; };

    // 0) preconvert weights to bf16 hi/lo
    preconv_k<<<(8 * SZ + 255) / 256, 256>>>(Wz, Wh, Wr, Ur, Wg, wh, wl);
    // 1) vocab tables pz, ph, pr, pgt
    tc_vocab<<<dim3(NX, yb(NV), 4), 256>>>(emb, wh, wl, bz, bh, bU, bg, pz, ph, pr, pgt);
    // 2) leaf message table + its Ur image
    mleaf_k<<<(NV * (HD / 2) + 255) / 256, 256>>>(pz, ph, mlf);
    tc_rur<<<dim3(NX, yb(NV)), 256>>>(mlf, wh + 5 * SZ, wl + 5 * SZ, rur);
    // 3) all leaves (nodes 16..31)
    leaf2_k<<<(NB * 16 * (HD / 2) + 255) / 256, 256>>>(wid, mlf, rur, pr, m, rm);

    // 4) interior levels: fused zh+mnew, then ur
    const int LO[4] = {15, 7, 3, 1};
    const int LG[4] = { 0, 3, 2, 1};
    for (int L = 0; L < 4; L++) {
        int lo = LO[L], lg = LG[L];
        int M = NB << lg;
        tc_zhm<<<dim3(NX, yb(M)), 256, SMEM_ZHM>>>(m, rm, wh + SZ, wl + SZ,
                                                   wh + 3 * SZ, wl + 3 * SZ,
                                                   wid, pz, ph, m, mh, ml, M, lo, lg);
        if (L < 3)
            tc_ur<<<dim3(NX, yb(M)), 256>>>(mh, ml, wh + 5 * SZ, wl + 5 * SZ,
                                            rm, M, lo, lg, wid, pr, m);
    }

    // 5) final: out[t] = relu(pgt[wid[t*32]] + (m[1]+m[2]) @ Wg_bot)
    tc_fin<<<dim3(NX, yb(NB)), 256>>>(m, wh + 7 * SZ, wl + 7 * SZ, out, wid, pgt);
}

// round 8
// speedup vs baseline: 1.1396x; 1.1396x over previous
#include <cuda_runtime.h>
#include <cuda_bf16.h>
#include <math.h>
#include <cstdint>

#define HD 450
#define HDP 464
#define NTREE 32
#define NB 1024
#define NNODE (NB*NTREE)
#define NV 780

// ---------------- scratch (static device memory) ----------------
__device__ float g_pz [NV*HD];
__device__ float g_ph [NV*HD];
__device__ float g_pr [NV*HD];
__device__ float g_pgt[NV*HD];
__device__ float g_mlf[NV*HD];
__device__ float g_rur[NV*HD];
__device__ float g_m  [NNODE*HD];
__device__ float g_rm [NNODE*HD];
__device__ float g_zp [NB*8*HD];
__device__ float g_hp [NB*8*HD];
__device__ __nv_bfloat16 g_mh[NNODE*HD];    // m split hi (interior nodes)
__device__ __nv_bfloat16 g_ml[NNODE*HD];    // m split lo
__device__ __nv_bfloat16 g_wh[8*HD*HDP];    // preconverted weights hi (padded stride)
__device__ __nv_bfloat16 g_wl[8*HD*HDP];    // preconverted weights lo
// slots: 0 Wz_top, 1 Wz_bot, 2 Wh_top, 3 Wh_bot, 4 Wr, 5 Ur, 6 Wg_top, 7 Wg_bot

// ================= helpers =================
constexpr int BM = 128, BN = 64, BK = 32;
constexpr int NCHK = (HD + BK - 1) / BK;   // 15
constexpr int ASTR = 40;   // 80B row stride (16B-aligned)
constexpr int BSTR = 72;   // 144B row stride (16B-aligned)

__device__ __forceinline__ void ldm_x4(uint32_t* r, uint32_t addr) {
    asm volatile("ldmatrix.sync.aligned.m8n8.x4.shared.b16 {%0,%1,%2,%3}, [%4];"
                 : "=r"(r[0]), "=r"(r[1]), "=r"(r[2]), "=r"(r[3]) : "r"(addr));
}
__device__ __forceinline__ void ldm_x2t(uint32_t* r, uint32_t addr) {
    asm volatile("ldmatrix.sync.aligned.m8n8.x2.trans.shared.b16 {%0,%1}, [%2];"
                 : "=r"(r[0]), "=r"(r[1]) : "r"(addr));
}
__device__ __forceinline__ void mma_bf16(float* c, const uint32_t* a, const uint32_t* b) {
    asm volatile("mma.sync.aligned.m16n8k16.row.col.f32.bf16.bf16.f32 "
                 "{%0,%1,%2,%3}, {%4,%5,%6,%7}, {%8,%9}, {%0,%1,%2,%3};"
                 : "+f"(c[0]), "+f"(c[1]), "+f"(c[2]), "+f"(c[3])
                 : "r"(a[0]), "r"(a[1]), "r"(a[2]), "r"(a[3]), "r"(b[0]), "r"(b[1]));
}
__device__ __forceinline__ void split2(float2 v, uint32_t& hi, uint32_t& lo) {
    __nv_bfloat162 h = __floats2bfloat162_rn(v.x, v.y);
    __nv_bfloat162 l = __floats2bfloat162_rn(v.x - __bfloat162float(h.x),
                                             v.y - __bfloat162float(h.y));
    hi = *(uint32_t*)&h;
    lo = *(uint32_t*)&l;
}
__device__ __forceinline__ void cp16(uint32_t smem, const void* g) {
    asm volatile("cp.async.cg.shared.global [%0], [%1], 16;" :: "r"(smem), "l"(g));
}
#define CP_COMMIT() asm volatile("cp.async.commit_group;")
#define CP_WAIT0()  asm volatile("cp.async.wait_group 0;" ::: "memory")

// ================= GEMM body =================
// C[M x 450] = gatherA[M x 450] @ W[450 x 450] (fp32 via bf16x3 split)
// AM: 0 dense fp32 A; 1 fp32 child-sum; 3 bf16 hi/lo node read (mh/ml)
// EPI: 0 plain; 1 +bias; 3 rm=sig(pr[wp]+acc)*msrc; 4 relu(ptab[w0]+acc)
template<int AM, int EPI>
__device__ __forceinline__ void gemm_body(
    const float* __restrict__ A,
    const __nv_bfloat16* __restrict__ Amh, const __nv_bfloat16* __restrict__ Aml,
    const __nv_bfloat16* __restrict__ Bhg, const __nv_bfloat16* __restrict__ Blg,
    const float* __restrict__ bias, float* __restrict__ C,
    int M, int lo, int lg,
    const int* __restrict__ wid, const float* __restrict__ ptab,
    const float* __restrict__ pr, const float* __restrict__ msrc)
{
    __shared__ __align__(16) __nv_bfloat16 Ah[BM * ASTR], Al[BM * ASTR];
    __shared__ __align__(16) __nv_bfloat16 Bh[BK * BSTR], Bl[BK * BSTR];

    const int tid = threadIdx.x;
    const int lane = tid & 31, wrp = tid >> 5;
    const int wm = wrp & 3, wn = wrp >> 2;
    const int n0 = blockIdx.x * BN, m0 = blockIdx.y * BM;

    const uint32_t sAh = (uint32_t)__cvta_generic_to_shared(Ah);
    const uint32_t sAl = (uint32_t)__cvta_generic_to_shared(Al);
    const uint32_t sBh = (uint32_t)__cvta_generic_to_shared(Bh);
    const uint32_t sBl = (uint32_t)__cvta_generic_to_shared(Bl);

    float acc[2][4][4] = {};

    const int q = lane >> 3, r8 = lane & 7;
    const int arow_off = (q & 1) * 8 + r8;
    const int acol_off = (q >> 1) * 8;
    const int l16 = lane & 15;
    const int bk_off = (l16 >> 3) * 8 + (l16 & 7);

    // B cp.async addressing: one 16B segment per thread per buffer
    const int bkk = tid >> 3, bseg = tid & 7;
    const uint32_t bDstH = sBh + (uint32_t)(bkk * BSTR + bseg * 8) * 2;
    const uint32_t bDstL = sBl + (uint32_t)(bkk * BSTR + bseg * 8) * 2;

    for (int c = 0; c < NCHK; c++) {
        __syncthreads();
        // ---- B tile via cp.async (free) ----
        {
            int k = c * BK + bkk;
            if (k < HD) {
                const __nv_bfloat16* gh = Bhg + k * HDP + n0 + bseg * 8;
                const __nv_bfloat16* gl = Blg + k * HDP + n0 + bseg * 8;
                cp16(bDstH, gh);
                cp16(bDstL, gl);
            } else {
                uint4 z = make_uint4(0, 0, 0, 0);
                *(uint4*)&Bh[bkk * BSTR + bseg * 8] = z;
                *(uint4*)&Bl[bkk * BSTR + bseg * 8] = z;
            }
        }
        CP_COMMIT();
        // ---- A tile fill (overlaps with B cp.async in flight) ----
#pragma unroll
        for (int i = 0; i < 8; i++) {
            int idx = tid + i * 256;
            int row = idx >> 4, col = (idx & 15) * 2;
            int k = c * BK + col, arow = m0 + row;
            uint32_t hp = 0, lp = 0;
            if (arow < M && k < HD) {
                if constexpr (AM == 3) {
                    int t = arow >> lg, ci = lo + (arow & ((1 << lg) - 1));
                    int g = (t * NTREE + ci) * HD + k;
                    hp = *(const uint32_t*)&Amh[g];
                    lp = *(const uint32_t*)&Aml[g];
                } else {
                    float2 v;
                    if constexpr (AM == 0) {
                        v = *(const float2*)&A[arow * HD + k];
                    } else {   // AM == 1 child-sum
                        int t = arow >> lg, ci = lo + (arow & ((1 << lg) - 1));
                        int c1 = 2 * ci + 1;
                        const float* p1 = &A[(t * NTREE + c1) * HD + k];
                        v = *(const float2*)p1;
                        if (c1 + 1 < NTREE) {
                            float2 u = *(const float2*)(p1 + HD);
                            v.x += u.x; v.y += u.y;
                        }
                    }
                    split2(v, hp, lp);
                }
            }
            *(uint32_t*)&Ah[row * ASTR + col] = hp;
            *(uint32_t*)&Al[row * ASTR + col] = lp;
        }
        CP_WAIT0();
        __syncthreads();

        // ---- MMA phase ----
#pragma unroll
        for (int ks = 0; ks < 2; ks++) {
            uint32_t ah[2][4], al[2][4], bh[4][2], bl[4][2];
#pragma unroll
            for (int mf = 0; mf < 2; mf++) {
                int row = wm * 32 + mf * 16 + arow_off;
                int col = ks * 16 + acol_off;
                uint32_t off = (uint32_t)(row * ASTR + col) * 2;
                ldm_x4(ah[mf], sAh + off);
                ldm_x4(al[mf], sAl + off);
            }
#pragma unroll
            for (int nf = 0; nf < 4; nf++) {
                int krow = ks * 16 + bk_off;
                uint32_t off = (uint32_t)(krow * BSTR + wn * 32 + nf * 8) * 2;
                ldm_x2t(bh[nf], sBh + off);
                ldm_x2t(bl[nf], sBl + off);
            }
#pragma unroll
            for (int mf = 0; mf < 2; mf++)
#pragma unroll
                for (int nf = 0; nf < 4; nf++) {
                    mma_bf16(acc[mf][nf], ah[mf], bh[nf]);
                    mma_bf16(acc[mf][nf], ah[mf], bl[nf]);
                    mma_bf16(acc[mf][nf], al[mf], bh[nf]);
                }
        }
    }

    // ---- epilogue ----
    const int gr = lane >> 2, gc = (lane & 3) * 2;
#pragma unroll
    for (int mf = 0; mf < 2; mf++) {
#pragma unroll
        for (int h = 0; h < 2; h++) {
            int arow = m0 + wm * 32 + mf * 16 + h * 8 + gr;
            if (arow >= M) continue;
            int g = 0, wp = 0, w0 = 0;
            if constexpr (EPI == 3) {
                int t = arow >> lg, ci = lo + (arow & ((1 << lg) - 1));
                g  = t * NTREE + ci;
                wp = wid[t * NTREE + ((ci - 1) >> 1)];
            } else if constexpr (EPI == 4) {
                w0 = wid[arow * NTREE];
            }
#pragma unroll
            for (int nf = 0; nf < 4; nf++) {
                int j = n0 + wn * 32 + nf * 8 + gc;
                if (j >= HD) continue;
                float vx = acc[mf][nf][h * 2];
                float vy = acc[mf][nf][h * 2 + 1];
                if constexpr (EPI == 0) {
                    *(float2*)&C[arow * HD + j] = make_float2(vx, vy);
                } else if constexpr (EPI == 1) {
                    float2 b = *(const float2*)&bias[j];
                    *(float2*)&C[arow * HD + j] = make_float2(vx + b.x, vy + b.y);
                } else if constexpr (EPI == 3) {
                    float2 pv = *(const float2*)&pr[wp * HD + j];
                    float2 mv = *(const float2*)&msrc[g * HD + j];
                    float rx = 1.f / (1.f + expf(-(pv.x + vx)));
                    float ry = 1.f / (1.f + expf(-(pv.y + vy)));
                    *(float2*)&C[g * HD + j] = make_float2(rx * mv.x, ry * mv.y);
                } else { // EPI == 4
                    float2 pv = *(const float2*)&ptab[w0 * HD + j];
                    *(float2*)&C[arow * HD + j] =
                        make_float2(fmaxf(pv.x + vx, 0.f), fmaxf(pv.y + vy, 0.f));
                }
            }
        }
    }
}

// ================= kernel wrappers =================
__global__ __launch_bounds__(256) void tc_vocab(
    const float* emb, const __nv_bfloat16* wh, const __nv_bfloat16* wl,
    const float* bz, const float* bh_, const float* bU, const float* bg,
    float* pz, float* ph_, float* pr, float* pgt)
{
    const int SZ = HD * HDP;
    const float* b; float* C; int slot;
    switch (blockIdx.z) {
        case 0:  slot = 0; b = bz;  C = pz;  break;
        case 1:  slot = 2; b = bh_; C = ph_; break;
        case 2:  slot = 4; b = bU;  C = pr;  break;
        default: slot = 6; b = bg;  C = pgt; break;
    }
    gemm_body<0, 1>(emb, nullptr, nullptr, wh + slot * SZ, wl + slot * SZ,
                    b, C, NV, 0, 0, nullptr, nullptr, nullptr, nullptr);
}

__global__ __launch_bounds__(256) void tc_rur(
    const float* mlf, const __nv_bfloat16* wh, const __nv_bfloat16* wl, float* rur)
{
    const int SZ = HD * HDP;
    gemm_body<0, 0>(mlf, nullptr, nullptr, wh + 5 * SZ, wl + 5 * SZ, nullptr, rur,
                    NV, 0, 0, nullptr, nullptr, nullptr, nullptr);
}

__global__ __launch_bounds__(256) void tc_zh(
    const float* m, const float* rm,
    const __nv_bfloat16* wh, const __nv_bfloat16* wl,
    float* zp, float* hp, int M, int lo, int lg)
{
    const int SZ = HD * HDP;
    if (blockIdx.z == 0)
        gemm_body<1, 0>(m, nullptr, nullptr, wh + 1 * SZ, wl + 1 * SZ, nullptr, zp,
                        M, lo, lg, nullptr, nullptr, nullptr, nullptr);
    else
        gemm_body<1, 0>(rm, nullptr, nullptr, wh + 3 * SZ, wl + 3 * SZ, nullptr, hp,
                        M, lo, lg, nullptr, nullptr, nullptr, nullptr);
}

__global__ __launch_bounds__(256) void tc_ur(
    const __nv_bfloat16* mhg, const __nv_bfloat16* mlg,
    const __nv_bfloat16* wh, const __nv_bfloat16* wl,
    float* rm, int M, int lo, int lg,
    const int* wid, const float* pr, const float* msrc)
{
    const int SZ = HD * HDP;
    gemm_body<3, 3>(nullptr, mhg, mlg, wh + 5 * SZ, wl + 5 * SZ, nullptr, rm,
                    M, lo, lg, wid, nullptr, pr, msrc);
}

__global__ __launch_bounds__(256) void tc_fin(
    const float* m, const __nv_bfloat16* wh, const __nv_bfloat16* wl,
    float* out, const int* wid, const float* pgt)
{
    const int SZ = HD * HDP;
    gemm_body<1, 4>(m, nullptr, nullptr, wh + 7 * SZ, wl + 7 * SZ, nullptr, out,
                    NB, 0, 0, wid, pgt, nullptr, nullptr);
}

// ================= elementwise / preconvert =================
__global__ void preconv_k(const float* __restrict__ Wz, const float* __restrict__ Wh,
                          const float* __restrict__ Wr, const float* __restrict__ Ur,
                          const float* __restrict__ Wg,
                          __nv_bfloat16* __restrict__ wh, __nv_bfloat16* __restrict__ wl)
{
    int idx = blockIdx.x * blockDim.x + threadIdx.x;
    const int SZ = HD * HDP;
    if (idx >= 8 * SZ) return;
    int slot = idx / SZ, off = idx - slot * SZ;
    int k = off / HDP, j = off - k * HDP;
    float v = 0.f;
    if (j < HD) {
        int src = k * HD + j;
        const int WSZ = HD * HD;
        switch (slot) {
            case 0:  v = Wz[src];       break;
            case 1:  v = Wz[WSZ + src]; break;
            case 2:  v = Wh[src];       break;
            case 3:  v = Wh[WSZ + src]; break;
            case 4:  v = Wr[src];       break;
            case 5:  v = Ur[src];       break;
            case 6:  v = Wg[src];       break;
            default: v = Wg[WSZ + src]; break;
        }
    }
    __nv_bfloat16 h = __float2bfloat16(v);
    wh[idx] = h;
    wl[idx] = __float2bfloat16(v - __bfloat162float(h));
}

__global__ void mleaf_k(const float* __restrict__ pz, const float* __restrict__ ph,
                        float* __restrict__ mlf)
{
    int idx = blockIdx.x * blockDim.x + threadIdx.x;
    if (idx >= NV * (HD / 2)) return;
    int j = idx * 2;
    float2 a = *(const float2*)&pz[j];
    float2 b = *(const float2*)&ph[j];
    float zx = 1.f / (1.f + expf(-a.x)), zy = 1.f / (1.f + expf(-a.y));
    *(float2*)&mlf[j] = make_float2(zx * tanhf(b.x), zy * tanhf(b.y));
}

__global__ void leaf2_k(const int* __restrict__ wid,
                        const float* __restrict__ mlf, const float* __restrict__ rur,
                        const float* __restrict__ pr,
                        float* __restrict__ m, float* __restrict__ rm)
{
    int idx = blockIdx.x * blockDim.x + threadIdx.x;
    const int TOT = NB * 16 * (HD / 2);
    if (idx >= TOT) return;
    int a = idx / (HD / 2);
    int j = (idx - a * (HD / 2)) * 2;
    int t = a >> 4, ci = 16 + (a & 15);
    int g = t * NTREE + ci;
    int w = wid[g];
    int wp = wid[t * NTREE + ((ci - 1) >> 1)];
    float2 mv = *(const float2*)&mlf[w * HD + j];
    float2 ru = *(const float2*)&rur[w * HD + j];
    float2 pv = *(const float2*)&pr[wp * HD + j];
    float rx = 1.f / (1.f + expf(-(pv.x + ru.x)));
    float ry = 1.f / (1.f + expf(-(pv.y + ru.y)));
    *(float2*)&m[g * HD + j]  = mv;
    *(float2*)&rm[g * HD + j] = make_float2(rx * mv.x, ry * mv.y);
}

// m_new + bf16 hi/lo split emit
__global__ void mnew2_k(const int* __restrict__ wid,
                        const float* __restrict__ pz, const float* __restrict__ ph,
                        const float* __restrict__ zp, const float* __restrict__ hp,
                        float* __restrict__ m,
                        __nv_bfloat16* __restrict__ mh, __nv_bfloat16* __restrict__ ml,
                        int lo, int lg, int total2)
{
    int idx = blockIdx.x * blockDim.x + threadIdx.x;
    if (idx >= total2) return;
    int row = idx / (HD / 2);
    int j = (idx - row * (HD / 2)) * 2;
    int t = row >> lg, ci = lo + (row & ((1 << lg) - 1));
    int g = t * NTREE + ci;
    int w = wid[g];
    float2 zpv = *(const float2*)&zp[row * HD + j];
    float2 hpv = *(const float2*)&hp[row * HD + j];
    float2 pzv = *(const float2*)&pz[w * HD + j];
    float2 phv = *(const float2*)&ph[w * HD + j];
    int c1 = 2 * ci + 1;
    float2 s = *(const float2*)&m[(t * NTREE + c1) * HD + j];
    if (c1 + 1 < NTREE) {
        float2 s2 = *(const float2*)&m[(t * NTREE + c1 + 1) * HD + j];
        s.x += s2.x; s.y += s2.y;
    }
    float zx = 1.f / (1.f + expf(-(pzv.x + zpv.x)));
    float zy = 1.f / (1.f + expf(-(pzv.y + zpv.y)));
    float tx = tanhf(phv.x + hpv.x);
    float ty = tanhf(phv.y + hpv.y);
    float2 o = make_float2((1.f - zx) * s.x + zx * tx,
                           (1.f - zy) * s.y + zy * ty);
    *(float2*)&m[g * HD + j] = o;
    uint32_t hi, lo2;
    split2(o, hi, lo2);
    *(uint32_t*)&mh[g * HD + j] = hi;
    *(uint32_t*)&ml[g * HD + j] = lo2;
}

// ================= launch =================
extern "C" void kernel_launch(void* const* d_in, const int* in_sizes, int n_in,
                              void* d_out, int out_size)
{
    const int*   wid = (const int*)  d_in[0];
    const float* emb = (const float*)d_in[1];
    const float* Wz  = (const float*)d_in[2];
    const float* bz  = (const float*)d_in[3];
    const float* Wr  = (const float*)d_in[4];
    const float* Ur  = (const float*)d_in[5];
    const float* bU  = (const float*)d_in[6];
    const float* Wh  = (const float*)d_in[7];
    const float* bh  = (const float*)d_in[8];
    const float* Wg  = (const float*)d_in[9];
    const float* bg  = (const float*)d_in[10];
    float* out = (float*)d_out;

    float *pz, *ph, *pr, *pgt, *mlf, *rur, *m, *rm, *zp, *hp;
    __nv_bfloat16 *mh, *ml, *wh, *wl;
    cudaGetSymbolAddress((void**)&pz,  g_pz);
    cudaGetSymbolAddress((void**)&ph,  g_ph);
    cudaGetSymbolAddress((void**)&pr,  g_pr);
    cudaGetSymbolAddress((void**)&pgt, g_pgt);
    cudaGetSymbolAddress((void**)&mlf, g_mlf);
    cudaGetSymbolAddress((void**)&rur, g_rur);
    cudaGetSymbolAddress((void**)&m,   g_m);
    cudaGetSymbolAddress((void**)&rm,  g_rm);
    cudaGetSymbolAddress((void**)&zp,  g_zp);
    cudaGetSymbolAddress((void**)&hp,  g_hp);
    cudaGetSymbolAddress((void**)&mh,  g_mh);
    cudaGetSymbolAddress((void**)&ml,  g_ml);
    cudaGetSymbolAddress((void**)&wh,  g_wh);
    cudaGetSymbolAddress((void**)&wl,  g_wl);

    const int NX = (HD + BN - 1) / BN;   // 8
    auto yb = [](int M) { return (M + BM - 1) / BM; };

    // 0) preconvert weights (padded bf16 hi/lo)
    preconv_k<<<(8 * HD * HDP + 255) / 256, 256>>>(Wz, Wh, Wr, Ur, Wg, wh, wl);
    // 1) vocab tables
    tc_vocab<<<dim3(NX, yb(NV), 4), 256>>>(emb, wh, wl, bz, bh, bU, bg, pz, ph, pr, pgt);
    // 2) leaf message table + its Ur image
    mleaf_k<<<(NV * (HD / 2) + 255) / 256, 256>>>(pz, ph, mlf);
    tc_rur<<<dim3(NX, yb(NV)), 256>>>(mlf, wh, wl, rur);
    // 3) all leaves
    leaf2_k<<<(NB * 16 * (HD / 2) + 255) / 256, 256>>>(wid, mlf, rur, pr, m, rm);

    // 4) interior levels
    const int LO[4] = {15, 7, 3, 1};
    const int LG[4] = { 0, 3, 2, 1};
    for (int L = 0; L < 4; L++) {
        int lo = LO[L], lg = LG[L];
        int M = NB << lg;
        int total2 = M * (HD / 2);
        tc_zh<<<dim3(NX, yb(M), 2), 256>>>(m, rm, wh, wl, zp, hp, M, lo, lg);
        mnew2_k<<<(total2 + 255) / 256, 256>>>(wid, pz, ph, zp, hp, m, mh, ml,
                                               lo, lg, total2);
        if (L < 3)
            tc_ur<<<dim3(NX, yb(M)), 256>>>(mh, ml, wh, wl, rm, M, lo, lg, wid, pr, m);
    }

    // 5) final
    tc_fin<<<dim3(NX, yb(NB)), 256>>>(m, wh, wl, out, wid, pgt);
}

// round 9
// speedup vs baseline: 1.9253x; 1.6896x over previous
#include <cuda_runtime.h>
#include <cuda_bf16.h>
#include <math.h>
#include <cstdint>

#define HD 450
#define HDP 464
#define NTREE 32
#define NB 1024
#define NNODE (NB*NTREE)
#define NV 780

// ---------------- scratch (static device memory) ----------------
__device__ float g_pz [NV*HD];
__device__ float g_ph [NV*HD];
__device__ float g_pr [NV*HD];
__device__ float g_pgt[NV*HD];
__device__ float g_mlf[NV*HD];
__device__ float g_rur[NV*HD];
__device__ float g_m  [NNODE*HD];
__device__ float g_rm [NNODE*HD];
__device__ float g_zp [NB*8*HD];
__device__ float g_hp [NB*8*HD];
// bf16 hi/lo split activations (dense rows, stride HDP, zero-padded)
__device__ __nv_bfloat16 g_eh  [NV*HDP],   g_el  [NV*HDP];    // emb
__device__ __nv_bfloat16 g_mlfh[NV*HDP],   g_mlfl[NV*HDP];    // leaf msg table
__device__ __nv_bfloat16 g_sh  [NB*8*HDP], g_sl  [NB*8*HDP];  // child-sum s
__device__ __nv_bfloat16 g_ah  [NB*8*HDP], g_al  [NB*8*HDP];  // child-sum arm
__device__ __nv_bfloat16 g_mdh [NB*8*HDP], g_mdl [NB*8*HDP];  // m_new (dense)
__device__ __nv_bfloat16 g_wh  [8*HD*HDP], g_wl  [8*HD*HDP];  // weights
// slots: 0 Wz_top, 1 Wz_bot, 2 Wh_top, 3 Wh_bot, 4 Wr, 5 Ur, 6 Wg_top, 7 Wg_bot

// ================= helpers =================
constexpr int BM = 128, BN = 64, BK = 32;
constexpr int NCHK = 15;           // ceil(450/32)
constexpr int ASTR = 40;           // bf16 elems per A smem row
constexpr int BSTR = 72;           // bf16 elems per B smem row
constexpr int STG  = 2*BM*ASTR + 2*BK*BSTR;   // elems per pipeline stage (14848)
constexpr int SMEMB = 2 * STG * 2;            // bytes for 2 stages (59392)

__device__ __forceinline__ void ldm_x4(uint32_t* r, uint32_t addr) {
    asm volatile("ldmatrix.sync.aligned.m8n8.x4.shared.b16 {%0,%1,%2,%3}, [%4];"
                 : "=r"(r[0]), "=r"(r[1]), "=r"(r[2]), "=r"(r[3]) : "r"(addr));
}
__device__ __forceinline__ void ldm_x2t(uint32_t* r, uint32_t addr) {
    asm volatile("ldmatrix.sync.aligned.m8n8.x2.trans.shared.b16 {%0,%1}, [%2];"
                 : "=r"(r[0]), "=r"(r[1]) : "r"(addr));
}
__device__ __forceinline__ void mma_bf16(float* c, const uint32_t* a, const uint32_t* b) {
    asm volatile("mma.sync.aligned.m16n8k16.row.col.f32.bf16.bf16.f32 "
                 "{%0,%1,%2,%3}, {%4,%5,%6,%7}, {%8,%9}, {%0,%1,%2,%3};"
                 : "+f"(c[0]), "+f"(c[1]), "+f"(c[2]), "+f"(c[3])
                 : "r"(a[0]), "r"(a[1]), "r"(a[2]), "r"(a[3]), "r"(b[0]), "r"(b[1]));
}
__device__ __forceinline__ void cp16(uint32_t smem, const void* g) {
    asm volatile("cp.async.cg.shared.global [%0], [%1], 16;" :: "r"(smem), "l"(g));
}
#define CP_COMMIT() asm volatile("cp.async.commit_group;")
#define CP_WAIT1()  asm volatile("cp.async.wait_group 1;" ::: "memory")

__device__ __forceinline__ void splitf(float v, __nv_bfloat16& h, __nv_bfloat16& l) {
    h = __float2bfloat16(v);
    l = __float2bfloat16(v - __bfloat162float(h));
}

// ================= GEMM body: fully cp.async, 2-stage pipeline =================
// C[M x 450] = A[M x 450] @ W[450 x 450] (fp32 via bf16x3 split), A pre-split dense.
// EPI: 0 plain; 1 +bias; 3 rm=sig(pr[wp]+acc)*msrc; 4 relu(ptab[w0]+acc)
template<int EPI>
__device__ __forceinline__ void gemm_body(
    const __nv_bfloat16* __restrict__ Agh, const __nv_bfloat16* __restrict__ Agl,
    const __nv_bfloat16* __restrict__ Bgh, const __nv_bfloat16* __restrict__ Bgl,
    const float* __restrict__ bias, float* __restrict__ C,
    int M, int lo, int lg,
    const int* __restrict__ wid, const float* __restrict__ ptab,
    const float* __restrict__ pr, const float* __restrict__ msrc)
{
    extern __shared__ __align__(16) __nv_bfloat16 smp[];
    const int tid = threadIdx.x;
    const int lane = tid & 31, wrp = tid >> 5;
    const int wm = wrp & 3, wn = wrp >> 2;
    const int n0 = blockIdx.x * BN, m0 = blockIdx.y * BM;

    float acc[2][4][4] = {};

    const int q = lane >> 3, r8 = lane & 7;
    const int arow_off = (q & 1) * 8 + r8;
    const int acol_off = (q >> 1) * 8;
    const int l16 = lane & 15;
    const int bk_off = (l16 >> 3) * 8 + (l16 & 7);

    auto fill = [&](int s, int c) {
        __nv_bfloat16* Ah = smp + s * STG;
        __nv_bfloat16* Al = Ah + BM * ASTR;
        __nv_bfloat16* Bh = Al + BM * ASTR;
        __nv_bfloat16* Bl = Bh + BK * BSTR;
        // A: 128 rows x 4 hi-segs (16B each) + same for lo; 2 iters x 256 thr
#pragma unroll
        for (int i = 0; i < 2; i++) {
            int idx = tid + i * 256;           // 0..511
            int row = idx >> 2, seg = idx & 3;
            int k = c * BK + seg * 8;
            int arow = m0 + row;
            __nv_bfloat16* dh = Ah + row * ASTR + seg * 8;
            __nv_bfloat16* dl = Al + row * ASTR + seg * 8;
            if (arow < M && k <= HDP - 8) {
                size_t gofs = (size_t)arow * HDP + k;
                cp16((uint32_t)__cvta_generic_to_shared(dh), Agh + gofs);
                cp16((uint32_t)__cvta_generic_to_shared(dl), Agl + gofs);
            } else {
                uint4 z = make_uint4(0, 0, 0, 0);
                *(uint4*)dh = z;
                *(uint4*)dl = z;
            }
        }
        // B: 32 k-rows x 8 segs; 256 thr -> 1 hi + 1 lo each
        {
            int kk = tid >> 3, seg = tid & 7;
            int k = c * BK + kk;
            __nv_bfloat16* dh = Bh + kk * BSTR + seg * 8;
            __nv_bfloat16* dl = Bl + kk * BSTR + seg * 8;
            if (k < HD) {
                size_t gofs = (size_t)k * HDP + n0 + seg * 8;
                cp16((uint32_t)__cvta_generic_to_shared(dh), Bgh + gofs);
                cp16((uint32_t)__cvta_generic_to_shared(dl), Bgl + gofs);
            } else {
                uint4 z = make_uint4(0, 0, 0, 0);
                *(uint4*)dh = z;
                *(uint4*)dl = z;
            }
        }
    };

    fill(0, 0);
    CP_COMMIT();
    for (int c = 0; c < NCHK; c++) {
        int st = c & 1;
        if (c + 1 < NCHK) fill(st ^ 1, c + 1);
        CP_COMMIT();          // group per chunk (possibly empty at tail)
        CP_WAIT1();           // chunk c's data resident
        __syncthreads();

        const uint32_t sAh = (uint32_t)__cvta_generic_to_shared(smp + st * STG);
        const uint32_t sAl = sAh + BM * ASTR * 2;
        const uint32_t sBh = sAl + BM * ASTR * 2;
        const uint32_t sBl = sBh + BK * BSTR * 2;
#pragma unroll
        for (int ks = 0; ks < 2; ks++) {
            uint32_t ah[2][4], al[2][4], bh[4][2], bl[4][2];
#pragma unroll
            for (int mf = 0; mf < 2; mf++) {
                int row = wm * 32 + mf * 16 + arow_off;
                int col = ks * 16 + acol_off;
                uint32_t off = (uint32_t)(row * ASTR + col) * 2;
                ldm_x4(ah[mf], sAh + off);
                ldm_x4(al[mf], sAl + off);
            }
#pragma unroll
            for (int nf = 0; nf < 4; nf++) {
                int krow = ks * 16 + bk_off;
                uint32_t off = (uint32_t)(krow * BSTR + wn * 32 + nf * 8) * 2;
                ldm_x2t(bh[nf], sBh + off);
                ldm_x2t(bl[nf], sBl + off);
            }
#pragma unroll
            for (int mf = 0; mf < 2; mf++)
#pragma unroll
                for (int nf = 0; nf < 4; nf++) {
                    mma_bf16(acc[mf][nf], ah[mf], bh[nf]);
                    mma_bf16(acc[mf][nf], ah[mf], bl[nf]);
                    mma_bf16(acc[mf][nf], al[mf], bh[nf]);
                }
        }
        __syncthreads();      // before refilling the stage just read
    }

    // ---- epilogue ----
    const int gr = lane >> 2, gc = (lane & 3) * 2;
#pragma unroll
    for (int mf = 0; mf < 2; mf++) {
#pragma unroll
        for (int h = 0; h < 2; h++) {
            int arow = m0 + wm * 32 + mf * 16 + h * 8 + gr;
            if (arow >= M) continue;
            int g = 0, wp = 0, w0 = 0;
            if constexpr (EPI == 3) {
                int t = arow >> lg, ci = lo + (arow & ((1 << lg) - 1));
                g  = t * NTREE + ci;
                wp = wid[t * NTREE + ((ci - 1) >> 1)];
            } else if constexpr (EPI == 4) {
                w0 = wid[arow * NTREE];
            }
#pragma unroll
            for (int nf = 0; nf < 4; nf++) {
                int j = n0 + wn * 32 + nf * 8 + gc;
                if (j >= HD) continue;
                float vx = acc[mf][nf][h * 2];
                float vy = acc[mf][nf][h * 2 + 1];
                if constexpr (EPI == 0) {
                    *(float2*)&C[arow * HD + j] = make_float2(vx, vy);
                } else if constexpr (EPI == 1) {
                    float2 b = *(const float2*)&bias[j];
                    *(float2*)&C[arow * HD + j] = make_float2(vx + b.x, vy + b.y);
                } else if constexpr (EPI == 3) {
                    float2 pv = *(const float2*)&pr[wp * HD + j];
                    float2 mv = *(const float2*)&msrc[g * HD + j];
                    float rx = 1.f / (1.f + expf(-(pv.x + vx)));
                    float ry = 1.f / (1.f + expf(-(pv.y + vy)));
                    *(float2*)&C[g * HD + j] = make_float2(rx * mv.x, ry * mv.y);
                } else { // EPI == 4
                    float2 pv = *(const float2*)&ptab[w0 * HD + j];
                    *(float2*)&C[arow * HD + j] =
                        make_float2(fmaxf(pv.x + vx, 0.f), fmaxf(pv.y + vy, 0.f));
                }
            }
        }
    }
}

// ================= kernel wrappers =================
__global__ __launch_bounds__(256) void tc_vocab(
    const __nv_bfloat16* eh, const __nv_bfloat16* el,
    const __nv_bfloat16* wh, const __nv_bfloat16* wl,
    const float* bz, const float* bh_, const float* bU, const float* bg,
    float* pz, float* ph_, float* pr, float* pgt)
{
    const int SZ = HD * HDP;
    const float* b; float* C; int slot;
    switch (blockIdx.z) {
        case 0:  slot = 0; b = bz;  C = pz;  break;
        case 1:  slot = 2; b = bh_; C = ph_; break;
        case 2:  slot = 4; b = bU;  C = pr;  break;
        default: slot = 6; b = bg;  C = pgt; break;
    }
    gemm_body<1>(eh, el, wh + slot * SZ, wl + slot * SZ, b, C,
                 NV, 0, 0, nullptr, nullptr, nullptr, nullptr);
}

__global__ __launch_bounds__(256) void tc_rur(
    const __nv_bfloat16* mlfh, const __nv_bfloat16* mlfl,
    const __nv_bfloat16* wh, const __nv_bfloat16* wl, float* rur)
{
    const int SZ = HD * HDP;
    gemm_body<0>(mlfh, mlfl, wh + 5 * SZ, wl + 5 * SZ, nullptr, rur,
                 NV, 0, 0, nullptr, nullptr, nullptr, nullptr);
}

__global__ __launch_bounds__(256) void tc_zh(
    const __nv_bfloat16* sh, const __nv_bfloat16* sl,
    const __nv_bfloat16* ah, const __nv_bfloat16* al,
    const __nv_bfloat16* wh, const __nv_bfloat16* wl,
    float* zp, float* hp, int M)
{
    const int SZ = HD * HDP;
    if (blockIdx.z == 0)
        gemm_body<0>(sh, sl, wh + 1 * SZ, wl + 1 * SZ, nullptr, zp,
                     M, 0, 0, nullptr, nullptr, nullptr, nullptr);
    else
        gemm_body<0>(ah, al, wh + 3 * SZ, wl + 3 * SZ, nullptr, hp,
                     M, 0, 0, nullptr, nullptr, nullptr, nullptr);
}

__global__ __launch_bounds__(256) void tc_ur(
    const __nv_bfloat16* mdh, const __nv_bfloat16* mdl,
    const __nv_bfloat16* wh, const __nv_bfloat16* wl,
    float* rm, int M, int lo, int lg,
    const int* wid, const float* pr, const float* msrc)
{
    const int SZ = HD * HDP;
    gemm_body<3>(mdh, mdl, wh + 5 * SZ, wl + 5 * SZ, nullptr, rm,
                 M, lo, lg, wid, nullptr, pr, msrc);
}

__global__ __launch_bounds__(256) void tc_fin(
    const __nv_bfloat16* sh, const __nv_bfloat16* sl,
    const __nv_bfloat16* wh, const __nv_bfloat16* wl,
    float* out, const int* wid, const float* pgt)
{
    const int SZ = HD * HDP;
    gemm_body<4>(sh, sl, wh + 7 * SZ, wl + 7 * SZ, nullptr, out,
                 NB, 0, 0, wid, pgt, nullptr, nullptr);
}

// ================= elementwise / producers =================
__global__ void preconv_k(const float* __restrict__ Wz, const float* __restrict__ Wh,
                          const float* __restrict__ Wr, const float* __restrict__ Ur,
                          const float* __restrict__ Wg,
                          __nv_bfloat16* __restrict__ wh, __nv_bfloat16* __restrict__ wl)
{
    int idx = blockIdx.x * blockDim.x + threadIdx.x;
    const int SZ = HD * HDP;
    if (idx >= 8 * SZ) return;
    int slot = idx / SZ, off = idx - slot * SZ;
    int k = off / HDP, j = off - k * HDP;
    float v = 0.f;
    if (j < HD) {
        int src = k * HD + j;
        const int WSZ = HD * HD;
        switch (slot) {
            case 0:  v = Wz[src];       break;
            case 1:  v = Wz[WSZ + src]; break;
            case 2:  v = Wh[src];       break;
            case 3:  v = Wh[WSZ + src]; break;
            case 4:  v = Wr[src];       break;
            case 5:  v = Ur[src];       break;
            case 6:  v = Wg[src];       break;
            default: v = Wg[WSZ + src]; break;
        }
    }
    splitf(v, wh[idx], wl[idx]);
}

__global__ void esplit_k(const float* __restrict__ emb,
                         __nv_bfloat16* __restrict__ eh, __nv_bfloat16* __restrict__ el)
{
    int idx = blockIdx.x * blockDim.x + threadIdx.x;
    if (idx >= NV * HDP) return;
    int row = idx / HDP, j = idx - row * HDP;
    float v = (j < HD) ? emb[row * HD + j] : 0.f;
    splitf(v, eh[idx], el[idx]);
}

__global__ void mleaf_k(const float* __restrict__ pz, const float* __restrict__ ph,
                        float* __restrict__ mlf,
                        __nv_bfloat16* __restrict__ mlfh, __nv_bfloat16* __restrict__ mlfl)
{
    int idx = blockIdx.x * blockDim.x + threadIdx.x;
    if (idx >= NV * HDP) return;
    int row = idx / HDP, j = idx - row * HDP;
    float v = 0.f;
    if (j < HD) {
        int s = row * HD + j;
        float z = 1.f / (1.f + expf(-pz[s]));
        v = z * tanhf(ph[s]);
        mlf[s] = v;
    }
    splitf(v, mlfh[idx], mlfl[idx]);
}

__global__ void leaf2_k(const int* __restrict__ wid,
                        const float* __restrict__ mlf, const float* __restrict__ rur,
                        const float* __restrict__ pr,
                        float* __restrict__ m, float* __restrict__ rm)
{
    int idx = blockIdx.x * blockDim.x + threadIdx.x;
    const int TOT = NB * 16 * (HD / 2);
    if (idx >= TOT) return;
    int a = idx / (HD / 2);
    int j = (idx - a * (HD / 2)) * 2;
    int t = a >> 4, ci = 16 + (a & 15);
    int g = t * NTREE + ci;
    int w = wid[g];
    int wp = wid[t * NTREE + ((ci - 1) >> 1)];
    float2 mv = *(const float2*)&mlf[w * HD + j];
    float2 ru = *(const float2*)&rur[w * HD + j];
    float2 pv = *(const float2*)&pr[wp * HD + j];
    float rx = 1.f / (1.f + expf(-(pv.x + ru.x)));
    float ry = 1.f / (1.f + expf(-(pv.y + ru.y)));
    *(float2*)&m[g * HD + j]  = mv;
    *(float2*)&rm[g * HD + j] = make_float2(rx * mv.x, ry * mv.y);
}

// child-sums s = m[c1]+m[c2], arm = rm[c1]+rm[c2], emitted as dense bf16 hi/lo
__global__ void sumsplit_k(const float* __restrict__ m, const float* __restrict__ rm,
                           __nv_bfloat16* __restrict__ sh, __nv_bfloat16* __restrict__ sl,
                           __nv_bfloat16* __restrict__ ah, __nv_bfloat16* __restrict__ al,
                           int lo, int lg, int M, int do_arm)
{
    int idx = blockIdx.x * blockDim.x + threadIdx.x;
    if (idx >= M * HDP) return;
    int row = idx / HDP, j = idx - row * HDP;
    float s = 0.f, a = 0.f;
    if (j < HD) {
        int t = row >> lg, ci = lo + (row & ((1 << lg) - 1));
        int c1 = 2 * ci + 1;
        int b = (t * NTREE + c1) * HD + j;
        s = m[b];
        if (do_arm) a = rm[b];
        if (c1 + 1 < NTREE) {
            s += m[b + HD];
            if (do_arm) a += rm[b + HD];
        }
    }
    splitf(s, sh[idx], sl[idx]);
    if (do_arm) splitf(a, ah[idx], al[idx]);
}

// m_new from zp/hp, writes node fp32 + dense bf16 hi/lo
__global__ void mnew_k(const int* __restrict__ wid,
                       const float* __restrict__ pz, const float* __restrict__ ph,
                       const float* __restrict__ zp, const float* __restrict__ hp,
                       float* __restrict__ m,
                       __nv_bfloat16* __restrict__ mdh, __nv_bfloat16* __restrict__ mdl,
                       int lo, int lg, int M)
{
    int idx = blockIdx.x * blockDim.x + threadIdx.x;
    if (idx >= M * HDP) return;
    int row = idx / HDP, j = idx - row * HDP;
    float o = 0.f;
    if (j < HD) {
        int t = row >> lg, ci = lo + (row & ((1 << lg) - 1));
        int g = t * NTREE + ci;
        int w = wid[g];
        float z  = 1.f / (1.f + expf(-(pz[w * HD + j] + zp[row * HD + j])));
        float th = tanhf(ph[w * HD + j] + hp[row * HD + j]);
        int c1 = 2 * ci + 1;
        float s = m[(t * NTREE + c1) * HD + j];
        if (c1 + 1 < NTREE) s += m[(t * NTREE + c1 + 1) * HD + j];
        o = (1.f - z) * s + z * th;
        m[g * HD + j] = o;
    }
    splitf(o, mdh[idx], mdl[idx]);
}

// ================= launch =================
extern "C" void kernel_launch(void* const* d_in, const int* in_sizes, int n_in,
                              void* d_out, int out_size)
{
    const int*   wid = (const int*)  d_in[0];
    const float* emb = (const float*)d_in[1];
    const float* Wz  = (const float*)d_in[2];
    const float* bz  = (const float*)d_in[3];
    const float* Wr  = (const float*)d_in[4];
    const float* Ur  = (const float*)d_in[5];
    const float* bU  = (const float*)d_in[6];
    const float* Wh  = (const float*)d_in[7];
    const float* bh  = (const float*)d_in[8];
    const float* Wg  = (const float*)d_in[9];
    const float* bg  = (const float*)d_in[10];
    float* out = (float*)d_out;

    float *pz, *ph, *pr, *pgt, *mlf, *rur, *m, *rm, *zp, *hp;
    __nv_bfloat16 *eh, *el, *mlfh, *mlfl, *sh, *sl, *ah, *al, *mdh, *mdl, *wh, *wl;
    cudaGetSymbolAddress((void**)&pz,  g_pz);
    cudaGetSymbolAddress((void**)&ph,  g_ph);
    cudaGetSymbolAddress((void**)&pr,  g_pr);
    cudaGetSymbolAddress((void**)&pgt, g_pgt);
    cudaGetSymbolAddress((void**)&mlf, g_mlf);
    cudaGetSymbolAddress((void**)&rur, g_rur);
    cudaGetSymbolAddress((void**)&m,   g_m);
    cudaGetSymbolAddress((void**)&rm,  g_rm);
    cudaGetSymbolAddress((void**)&zp,  g_zp);
    cudaGetSymbolAddress((void**)&hp,  g_hp);
    cudaGetSymbolAddress((void**)&eh,  g_eh);
    cudaGetSymbolAddress((void**)&el,  g_el);
    cudaGetSymbolAddress((void**)&mlfh, g_mlfh);
    cudaGetSymbolAddress((void**)&mlfl, g_mlfl);
    cudaGetSymbolAddress((void**)&sh,  g_sh);
    cudaGetSymbolAddress((void**)&sl,  g_sl);
    cudaGetSymbolAddress((void**)&ah,  g_ah);
    cudaGetSymbolAddress((void**)&al,  g_al);
    cudaGetSymbolAddress((void**)&mdh, g_mdh);
    cudaGetSymbolAddress((void**)&mdl, g_mdl);
    cudaGetSymbolAddress((void**)&wh,  g_wh);
    cudaGetSymbolAddress((void**)&wl,  g_wl);

    cudaFuncSetAttribute(tc_vocab, cudaFuncAttributeMaxDynamicSharedMemorySize, SMEMB);
    cudaFuncSetAttribute(tc_rur,   cudaFuncAttributeMaxDynamicSharedMemorySize, SMEMB);
    cudaFuncSetAttribute(tc_zh,    cudaFuncAttributeMaxDynamicSharedMemorySize, SMEMB);
    cudaFuncSetAttribute(tc_ur,    cudaFuncAttributeMaxDynamicSharedMemorySize, SMEMB);
    cudaFuncSetAttribute(tc_fin,   cudaFuncAttributeMaxDynamicSharedMemorySize, SMEMB);

    const int NX = (HD + BN - 1) / BN;   // 8
    auto yb = [](int M) { return (M + BM - 1) / BM; };
    auto gb = [](int n) { return (n + 255) / 256; };

    // 0) preconvert weights + emb split
    preconv_k<<<gb(8 * HD * HDP), 256>>>(Wz, Wh, Wr, Ur, Wg, wh, wl);
    esplit_k<<<gb(NV * HDP), 256>>>(emb, eh, el);
    // 1) vocab tables
    tc_vocab<<<dim3(NX, yb(NV), 4), 256, SMEMB>>>(eh, el, wh, wl,
                                                  bz, bh, bU, bg, pz, ph, pr, pgt);
    // 2) leaf message table + its Ur image
    mleaf_k<<<gb(NV * HDP), 256>>>(pz, ph, mlf, mlfh, mlfl);
    tc_rur<<<dim3(NX, yb(NV)), 256, SMEMB>>>(mlfh, mlfl, wh, wl, rur);
    // 3) all leaves
    leaf2_k<<<gb(NB * 16 * (HD / 2)), 256>>>(wid, mlf, rur, pr, m, rm);

    // 4) interior levels
    const int LO[4] = {15, 7, 3, 1};
    const int LG[4] = { 0, 3, 2, 1};
    for (int L = 0; L < 4; L++) {
        int lo = LO[L], lg = LG[L];
        int M = NB << lg;
        sumsplit_k<<<gb(M * HDP), 256>>>(m, rm, sh, sl, ah, al, lo, lg, M, 1);
        tc_zh<<<dim3(NX, yb(M), 2), 256, SMEMB>>>(sh, sl, ah, al, wh, wl, zp, hp, M);
        mnew_k<<<gb(M * HDP), 256>>>(wid, pz, ph, zp, hp, m, mdh, mdl, lo, lg, M);
        if (L < 3)
            tc_ur<<<dim3(NX, yb(M)), 256, SMEMB>>>(mdh, mdl, wh, wl,
                                                   rm, M, lo, lg, wid, pr, m);
    }

    // 5) final: root child-sum then out = relu(pgt[wid_root] + s_root @ Wg_bot)
    sumsplit_k<<<gb(NB * HDP), 256>>>(m, rm, sh, sl, ah, al, 0, 0, NB, 0);
    tc_fin<<<dim3(NX, yb(NB)), 256, SMEMB>>>(sh, sl, wh, wl, out, wid, pgt);
}

// round 10
// speedup vs baseline: 2.0781x; 1.0793x over previous
#include <cuda_runtime.h>
#include <cuda_bf16.h>
#include <math.h>
#include <cstdint>

#define HD 450
#define HDP 464
#define NTREE 32
#define NB 1024
#define NNODE (NB*NTREE)
#define NV 780

// ---------------- scratch (static device memory) ----------------
__device__ float g_pz [NV*HD];
__device__ float g_ph [NV*HD];
__device__ float g_pr [NV*HD];
__device__ float g_pgt[NV*HD];
__device__ float g_mlf[NV*HD];
__device__ float g_rur[NV*HD];
__device__ float g_m  [NNODE*HD];
__device__ float g_rm [NNODE*HD];
__device__ float g_zp [NB*8*HD];
__device__ float g_hp [NB*8*HD];
// bf16 hi/lo split activations (dense rows, stride HDP, zero-padded)
__device__ __nv_bfloat16 g_eh  [NV*HDP],   g_el  [NV*HDP];
__device__ __nv_bfloat16 g_mlfh[NV*HDP],   g_mlfl[NV*HDP];
__device__ __nv_bfloat16 g_sh  [NB*8*HDP], g_sl  [NB*8*HDP];
__device__ __nv_bfloat16 g_ah  [NB*8*HDP], g_al  [NB*8*HDP];
__device__ __nv_bfloat16 g_mdh [NB*8*HDP], g_mdl [NB*8*HDP];
__device__ __nv_bfloat16 g_wh  [8*HD*HDP], g_wl  [8*HD*HDP];
// slots: 0 Wz_top, 1 Wz_bot, 2 Wh_top, 3 Wh_bot, 4 Wr, 5 Ur, 6 Wg_top, 7 Wg_bot

// ================= helpers =================
constexpr int BM = 128, BN = 64, BK = 64;
constexpr int NCHK = 8;            // ceil(450/64)
constexpr int ASTR = 72;           // bf16 elems per A smem row (BK + 8 pad)
constexpr int BSTR = 72;           // bf16 elems per B smem row (BN + 8 pad)
constexpr int STG  = 2*BM*ASTR + 2*BK*BSTR;   // elems per stage (27648)
constexpr int SMEMB = 2 * STG * 2;            // 110592 bytes, 2 stages

__device__ __forceinline__ void ldm_x4(uint32_t* r, uint32_t addr) {
    asm volatile("ldmatrix.sync.aligned.m8n8.x4.shared.b16 {%0,%1,%2,%3}, [%4];"
                 : "=r"(r[0]), "=r"(r[1]), "=r"(r[2]), "=r"(r[3]) : "r"(addr));
}
__device__ __forceinline__ void ldm_x2t(uint32_t* r, uint32_t addr) {
    asm volatile("ldmatrix.sync.aligned.m8n8.x2.trans.shared.b16 {%0,%1}, [%2];"
                 : "=r"(r[0]), "=r"(r[1]) : "r"(addr));
}
__device__ __forceinline__ void mma_bf16(float* c, const uint32_t* a, const uint32_t* b) {
    asm volatile("mma.sync.aligned.m16n8k16.row.col.f32.bf16.bf16.f32 "
                 "{%0,%1,%2,%3}, {%4,%5,%6,%7}, {%8,%9}, {%0,%1,%2,%3};"
                 : "+f"(c[0]), "+f"(c[1]), "+f"(c[2]), "+f"(c[3])
                 : "r"(a[0]), "r"(a[1]), "r"(a[2]), "r"(a[3]), "r"(b[0]), "r"(b[1]));
}
__device__ __forceinline__ void cp16(uint32_t smem, const void* g) {
    asm volatile("cp.async.cg.shared.global [%0], [%1], 16;" :: "r"(smem), "l"(g));
}
#define CP_COMMIT() asm volatile("cp.async.commit_group;")
#define CP_WAIT1()  asm volatile("cp.async.wait_group 1;" ::: "memory")

__device__ __forceinline__ void splitf(float v, __nv_bfloat16& h, __nv_bfloat16& l) {
    h = __float2bfloat16(v);
    l = __float2bfloat16(v - __bfloat162float(h));
}
__device__ __forceinline__ void split2u(float2 v, uint32_t& hi, uint32_t& lo) {
    __nv_bfloat162 h = __floats2bfloat162_rn(v.x, v.y);
    __nv_bfloat162 l = __floats2bfloat162_rn(v.x - __bfloat162float(h.x),
                                             v.y - __bfloat162float(h.y));
    hi = *(uint32_t*)&h;
    lo = *(uint32_t*)&l;
}

// ================= GEMM body: all-cp.async, 2-stage, BK=64 =================
// C[M x 450] = A[M x 450] @ W[450 x 450] (fp32 via bf16x3 split), A pre-split dense.
// EPI: 0 plain; 1 +bias; 3 rm=sig(pr[wp]+acc)*msrc; 4 relu(ptab[w0]+acc)
template<int EPI>
__device__ __forceinline__ void gemm_body(
    const __nv_bfloat16* __restrict__ Agh, const __nv_bfloat16* __restrict__ Agl,
    const __nv_bfloat16* __restrict__ Bgh, const __nv_bfloat16* __restrict__ Bgl,
    const float* __restrict__ bias, float* __restrict__ C,
    int M, int lo, int lg,
    const int* __restrict__ wid, const float* __restrict__ ptab,
    const float* __restrict__ pr, const float* __restrict__ msrc)
{
    extern __shared__ __align__(16) __nv_bfloat16 smp[];
    const int tid = threadIdx.x;
    const int lane = tid & 31, wrp = tid >> 5;
    const int wm = wrp & 3, wn = wrp >> 2;
    const int n0 = blockIdx.x * BN, m0 = blockIdx.y * BM;

    float acc[2][4][4] = {};

    const int q = lane >> 3, r8 = lane & 7;
    const int arow_off = (q & 1) * 8 + r8;
    const int acol_off = (q >> 1) * 8;
    const int l16 = lane & 15;
    const int bk_off = (l16 >> 3) * 8 + (l16 & 7);

    auto fill = [&](int s, int c) {
        __nv_bfloat16* Ah = smp + s * STG;
        __nv_bfloat16* Al = Ah + BM * ASTR;
        __nv_bfloat16* Bh = Al + BM * ASTR;
        __nv_bfloat16* Bl = Bh + BK * BSTR;
        // A: 128 rows x 8 segs (16B); 4 iters x 256 thr
#pragma unroll
        for (int i = 0; i < 4; i++) {
            int idx = tid + i * 256;           // 0..1023
            int row = idx >> 3, seg = idx & 7;
            int k = c * BK + seg * 8;
            int arow = m0 + row;
            __nv_bfloat16* dh = Ah + row * ASTR + seg * 8;
            __nv_bfloat16* dl = Al + row * ASTR + seg * 8;
            if (arow < M && k <= HDP - 8) {
                size_t gofs = (size_t)arow * HDP + k;
                cp16((uint32_t)__cvta_generic_to_shared(dh), Agh + gofs);
                cp16((uint32_t)__cvta_generic_to_shared(dl), Agl + gofs);
            } else {
                uint4 z = make_uint4(0, 0, 0, 0);
                *(uint4*)dh = z;
                *(uint4*)dl = z;
            }
        }
        // B: 64 k-rows x 8 segs; 2 iters x 256 thr
#pragma unroll
        for (int i = 0; i < 2; i++) {
            int idx = tid + i * 256;           // 0..511
            int kk = idx >> 3, seg = idx & 7;
            int k = c * BK + kk;
            __nv_bfloat16* dh = Bh + kk * BSTR + seg * 8;
            __nv_bfloat16* dl = Bl + kk * BSTR + seg * 8;
            if (k < HD) {
                size_t gofs = (size_t)k * HDP + n0 + seg * 8;
                cp16((uint32_t)__cvta_generic_to_shared(dh), Bgh + gofs);
                cp16((uint32_t)__cvta_generic_to_shared(dl), Bgl + gofs);
            } else {
                uint4 z = make_uint4(0, 0, 0, 0);
                *(uint4*)dh = z;
                *(uint4*)dl = z;
            }
        }
    };

    fill(0, 0);
    CP_COMMIT();
    for (int c = 0; c < NCHK; c++) {
        int st = c & 1;
        if (c + 1 < NCHK) fill(st ^ 1, c + 1);
        CP_COMMIT();
        CP_WAIT1();
        __syncthreads();

        const uint32_t sAh = (uint32_t)__cvta_generic_to_shared(smp + st * STG);
        const uint32_t sAl = sAh + BM * ASTR * 2;
        const uint32_t sBh = sAl + BM * ASTR * 2;
        const uint32_t sBl = sBh + BK * BSTR * 2;
#pragma unroll
        for (int ks = 0; ks < 4; ks++) {
            uint32_t ah[2][4], al[2][4], bh[4][2], bl[4][2];
#pragma unroll
            for (int mf = 0; mf < 2; mf++) {
                int row = wm * 32 + mf * 16 + arow_off;
                int col = ks * 16 + acol_off;
                uint32_t off = (uint32_t)(row * ASTR + col) * 2;
                ldm_x4(ah[mf], sAh + off);
                ldm_x4(al[mf], sAl + off);
            }
#pragma unroll
            for (int nf = 0; nf < 4; nf++) {
                int krow = ks * 16 + bk_off;
                uint32_t off = (uint32_t)(krow * BSTR + wn * 32 + nf * 8) * 2;
                ldm_x2t(bh[nf], sBh + off);
                ldm_x2t(bl[nf], sBl + off);
            }
#pragma unroll
            for (int mf = 0; mf < 2; mf++)
#pragma unroll
                for (int nf = 0; nf < 4; nf++) {
                    mma_bf16(acc[mf][nf], ah[mf], bh[nf]);
                    mma_bf16(acc[mf][nf], ah[mf], bl[nf]);
                    mma_bf16(acc[mf][nf], al[mf], bh[nf]);
                }
        }
        __syncthreads();
    }

    // ---- epilogue ----
    const int gr = lane >> 2, gc = (lane & 3) * 2;
#pragma unroll
    for (int mf = 0; mf < 2; mf++) {
#pragma unroll
        for (int h = 0; h < 2; h++) {
            int arow = m0 + wm * 32 + mf * 16 + h * 8 + gr;
            if (arow >= M) continue;
            int g = 0, wp = 0, w0 = 0;
            if constexpr (EPI == 3) {
                int t = arow >> lg, ci = lo + (arow & ((1 << lg) - 1));
                g  = t * NTREE + ci;
                wp = wid[t * NTREE + ((ci - 1) >> 1)];
            } else if constexpr (EPI == 4) {
                w0 = wid[arow * NTREE];
            }
#pragma unroll
            for (int nf = 0; nf < 4; nf++) {
                int j = n0 + wn * 32 + nf * 8 + gc;
                if (j >= HD) continue;
                float vx = acc[mf][nf][h * 2];
                float vy = acc[mf][nf][h * 2 + 1];
                if constexpr (EPI == 0) {
                    *(float2*)&C[arow * HD + j] = make_float2(vx, vy);
                } else if constexpr (EPI == 1) {
                    float2 b = *(const float2*)&bias[j];
                    *(float2*)&C[arow * HD + j] = make_float2(vx + b.x, vy + b.y);
                } else if constexpr (EPI == 3) {
                    float2 pv = *(const float2*)&pr[wp * HD + j];
                    float2 mv = *(const float2*)&msrc[g * HD + j];
                    float rx = 1.f / (1.f + expf(-(pv.x + vx)));
                    float ry = 1.f / (1.f + expf(-(pv.y + vy)));
                    *(float2*)&C[g * HD + j] = make_float2(rx * mv.x, ry * mv.y);
                } else { // EPI == 4
                    float2 pv = *(const float2*)&ptab[w0 * HD + j];
                    *(float2*)&C[arow * HD + j] =
                        make_float2(fmaxf(pv.x + vx, 0.f), fmaxf(pv.y + vy, 0.f));
                }
            }
        }
    }
}

// ================= kernel wrappers =================
__global__ __launch_bounds__(256) void tc_vocab(
    const __nv_bfloat16* eh, const __nv_bfloat16* el,
    const __nv_bfloat16* wh, const __nv_bfloat16* wl,
    const float* bz, const float* bh_, const float* bU, const float* bg,
    float* pz, float* ph_, float* pr, float* pgt)
{
    const int SZ = HD * HDP;
    const float* b; float* C; int slot;
    switch (blockIdx.z) {
        case 0:  slot = 0; b = bz;  C = pz;  break;
        case 1:  slot = 2; b = bh_; C = ph_; break;
        case 2:  slot = 4; b = bU;  C = pr;  break;
        default: slot = 6; b = bg;  C = pgt; break;
    }
    gemm_body<1>(eh, el, wh + slot * SZ, wl + slot * SZ, b, C,
                 NV, 0, 0, nullptr, nullptr, nullptr, nullptr);
}

__global__ __launch_bounds__(256) void tc_rur(
    const __nv_bfloat16* mlfh, const __nv_bfloat16* mlfl,
    const __nv_bfloat16* wh, const __nv_bfloat16* wl, float* rur)
{
    const int SZ = HD * HDP;
    gemm_body<0>(mlfh, mlfl, wh + 5 * SZ, wl + 5 * SZ, nullptr, rur,
                 NV, 0, 0, nullptr, nullptr, nullptr, nullptr);
}

__global__ __launch_bounds__(256) void tc_zh(
    const __nv_bfloat16* sh, const __nv_bfloat16* sl,
    const __nv_bfloat16* ah, const __nv_bfloat16* al,
    const __nv_bfloat16* wh, const __nv_bfloat16* wl,
    float* zp, float* hp, int M)
{
    const int SZ = HD * HDP;
    if (blockIdx.z == 0)
        gemm_body<0>(sh, sl, wh + 1 * SZ, wl + 1 * SZ, nullptr, zp,
                     M, 0, 0, nullptr, nullptr, nullptr, nullptr);
    else
        gemm_body<0>(ah, al, wh + 3 * SZ, wl + 3 * SZ, nullptr, hp,
                     M, 0, 0, nullptr, nullptr, nullptr, nullptr);
}

__global__ __launch_bounds__(256) void tc_ur(
    const __nv_bfloat16* mdh, const __nv_bfloat16* mdl,
    const __nv_bfloat16* wh, const __nv_bfloat16* wl,
    float* rm, int M, int lo, int lg,
    const int* wid, const float* pr, const float* msrc)
{
    const int SZ = HD * HDP;
    gemm_body<3>(mdh, mdl, wh + 5 * SZ, wl + 5 * SZ, nullptr, rm,
                 M, lo, lg, wid, nullptr, pr, msrc);
}

__global__ __launch_bounds__(256) void tc_fin(
    const __nv_bfloat16* sh, const __nv_bfloat16* sl,
    const __nv_bfloat16* wh, const __nv_bfloat16* wl,
    float* out, const int* wid, const float* pgt)
{
    const int SZ = HD * HDP;
    gemm_body<4>(sh, sl, wh + 7 * SZ, wl + 7 * SZ, nullptr, out,
                 NB, 0, 0, wid, pgt, nullptr, nullptr);
}

// ================= producers (2 elems / thread) =================
__global__ void preconv_k(const float* __restrict__ Wz, const float* __restrict__ Wh,
                          const float* __restrict__ Wr, const float* __restrict__ Ur,
                          const float* __restrict__ Wg,
                          __nv_bfloat16* __restrict__ wh, __nv_bfloat16* __restrict__ wl)
{
    int idx = blockIdx.x * blockDim.x + threadIdx.x;
    const int SZ2 = HD * HDP / 2;
    if (idx >= 8 * SZ2) return;
    int slot = idx / SZ2, off = idx - slot * SZ2;
    int k = off / (HDP / 2), j = (off - k * (HDP / 2)) * 2;
    float2 v = make_float2(0.f, 0.f);
    if (j < HD) {
        int src = k * HD + j;
        const int WSZ = HD * HD;
        switch (slot) {
            case 0:  v = *(const float2*)&Wz[src];       break;
            case 1:  v = *(const float2*)&Wz[WSZ + src]; break;
            case 2:  v = *(const float2*)&Wh[src];       break;
            case 3:  v = *(const float2*)&Wh[WSZ + src]; break;
            case 4:  v = *(const float2*)&Wr[src];       break;
            case 5:  v = *(const float2*)&Ur[src];       break;
            case 6:  v = *(const float2*)&Wg[src];       break;
            default: v = *(const float2*)&Wg[WSZ + src]; break;
        }
    }
    uint32_t hi, lo;
    split2u(v, hi, lo);
    int d = slot * HD * HDP + k * HDP + j;
    *(uint32_t*)&wh[d] = hi;
    *(uint32_t*)&wl[d] = lo;
}

__global__ void esplit_k(const float* __restrict__ emb,
                         __nv_bfloat16* __restrict__ eh, __nv_bfloat16* __restrict__ el)
{
    int idx = blockIdx.x * blockDim.x + threadIdx.x;
    if (idx >= NV * HDP / 2) return;
    int row = idx / (HDP / 2), j = (idx - row * (HDP / 2)) * 2;
    float2 v = (j < HD) ? *(const float2*)&emb[row * HD + j] : make_float2(0.f, 0.f);
    uint32_t hi, lo;
    split2u(v, hi, lo);
    *(uint32_t*)&eh[row * HDP + j] = hi;
    *(uint32_t*)&el[row * HDP + j] = lo;
}

__global__ void mleaf_k(const float* __restrict__ pz, const float* __restrict__ ph,
                        float* __restrict__ mlf,
                        __nv_bfloat16* __restrict__ mlfh, __nv_bfloat16* __restrict__ mlfl)
{
    int idx = blockIdx.x * blockDim.x + threadIdx.x;
    if (idx >= NV * HDP / 2) return;
    int row = idx / (HDP / 2), j = (idx - row * (HDP / 2)) * 2;
    float2 v = make_float2(0.f, 0.f);
    if (j < HD) {
        int s = row * HD + j;
        float2 a = *(const float2*)&pz[s];
        float2 b = *(const float2*)&ph[s];
        v.x = tanhf(b.x) / (1.f + expf(-a.x));
        v.y = tanhf(b.y) / (1.f + expf(-a.y));
        *(float2*)&mlf[s] = v;
    }
    uint32_t hi, lo;
    split2u(v, hi, lo);
    *(uint32_t*)&mlfh[row * HDP + j] = hi;
    *(uint32_t*)&mlfl[row * HDP + j] = lo;
}

__global__ void leaf2_k(const int* __restrict__ wid,
                        const float* __restrict__ mlf, const float* __restrict__ rur,
                        const float* __restrict__ pr,
                        float* __restrict__ m, float* __restrict__ rm)
{
    int idx = blockIdx.x * blockDim.x + threadIdx.x;
    const int TOT = NB * 16 * (HD / 2);
    if (idx >= TOT) return;
    int a = idx / (HD / 2);
    int j = (idx - a * (HD / 2)) * 2;
    int t = a >> 4, ci = 16 + (a & 15);
    int g = t * NTREE + ci;
    int w = wid[g];
    int wp = wid[t * NTREE + ((ci - 1) >> 1)];
    float2 mv = *(const float2*)&mlf[w * HD + j];
    float2 ru = *(const float2*)&rur[w * HD + j];
    float2 pv = *(const float2*)&pr[wp * HD + j];
    float rx = 1.f / (1.f + expf(-(pv.x + ru.x)));
    float ry = 1.f / (1.f + expf(-(pv.y + ru.y)));
    *(float2*)&m[g * HD + j]  = mv;
    *(float2*)&rm[g * HD + j] = make_float2(rx * mv.x, ry * mv.y);
}

__global__ void sumsplit_k(const float* __restrict__ m, const float* __restrict__ rm,
                           __nv_bfloat16* __restrict__ sh, __nv_bfloat16* __restrict__ sl,
                           __nv_bfloat16* __restrict__ ah, __nv_bfloat16* __restrict__ al,
                           int lo, int lg, int M, int do_arm)
{
    int idx = blockIdx.x * blockDim.x + threadIdx.x;
    if (idx >= M * (HDP / 2)) return;
    int row = idx / (HDP / 2), j = (idx - row * (HDP / 2)) * 2;
    float2 s = make_float2(0.f, 0.f), a = s;
    if (j < HD) {
        int t = row >> lg, ci = lo + (row & ((1 << lg) - 1));
        int c1 = 2 * ci + 1;
        int b = (t * NTREE + c1) * HD + j;
        s = *(const float2*)&m[b];
        if (do_arm) a = *(const float2*)&rm[b];
        if (c1 + 1 < NTREE) {
            float2 s2 = *(const float2*)&m[b + HD];
            s.x += s2.x; s.y += s2.y;
            if (do_arm) {
                float2 a2 = *(const float2*)&rm[b + HD];
                a.x += a2.x; a.y += a2.y;
            }
        }
    }
    uint32_t hi, lo2;
    int d = row * HDP + j;
    split2u(s, hi, lo2);
    *(uint32_t*)&sh[d] = hi;
    *(uint32_t*)&sl[d] = lo2;
    if (do_arm) {
        split2u(a, hi, lo2);
        *(uint32_t*)&ah[d] = hi;
        *(uint32_t*)&al[d] = lo2;
    }
}

__global__ void mnew_k(const int* __restrict__ wid,
                       const float* __restrict__ pz, const float* __restrict__ ph,
                       const float* __restrict__ zp, const float* __restrict__ hp,
                       float* __restrict__ m,
                       __nv_bfloat16* __restrict__ mdh, __nv_bfloat16* __restrict__ mdl,
                       int lo, int lg, int M)
{
    int idx = blockIdx.x * blockDim.x + threadIdx.x;
    if (idx >= M * (HDP / 2)) return;
    int row = idx / (HDP / 2), j = (idx - row * (HDP / 2)) * 2;
    float2 o = make_float2(0.f, 0.f);
    if (j < HD) {
        int t = row >> lg, ci = lo + (row & ((1 << lg) - 1));
        int g = t * NTREE + ci;
        int w = wid[g];
        float2 pzv = *(const float2*)&pz[w * HD + j];
        float2 phv = *(const float2*)&ph[w * HD + j];
        float2 zpv = *(const float2*)&zp[row * HD + j];
        float2 hpv = *(const float2*)&hp[row * HD + j];
        int c1 = 2 * ci + 1;
        float2 s = *(const float2*)&m[(t * NTREE + c1) * HD + j];
        if (c1 + 1 < NTREE) {
            float2 s2 = *(const float2*)&m[(t * NTREE + c1 + 1) * HD + j];
            s.x += s2.x; s.y += s2.y;
        }
        float zx = 1.f / (1.f + expf(-(pzv.x + zpv.x)));
        float zy = 1.f / (1.f + expf(-(pzv.y + zpv.y)));
        o.x = (1.f - zx) * s.x + zx * tanhf(phv.x + hpv.x);
        o.y = (1.f - zy) * s.y + zy * tanhf(phv.y + hpv.y);
        *(float2*)&m[g * HD + j] = o;
    }
    uint32_t hi, lo2;
    split2u(o, hi, lo2);
    *(uint32_t*)&mdh[row * HDP + j] = hi;
    *(uint32_t*)&mdl[row * HDP + j] = lo2;
}

// ================= launch =================
extern "C" void kernel_launch(void* const* d_in, const int* in_sizes, int n_in,
                              void* d_out, int out_size)
{
    const int*   wid = (const int*)  d_in[0];
    const float* emb = (const float*)d_in[1];
    const float* Wz  = (const float*)d_in[2];
    const float* bz  = (const float*)d_in[3];
    const float* Wr  = (const float*)d_in[4];
    const float* Ur  = (const float*)d_in[5];
    const float* bU  = (const float*)d_in[6];
    const float* Wh  = (const float*)d_in[7];
    const float* bh  = (const float*)d_in[8];
    const float* Wg  = (const float*)d_in[9];
    const float* bg  = (const float*)d_in[10];
    float* out = (float*)d_out;

    float *pz, *ph, *pr, *pgt, *mlf, *rur, *m, *rm, *zp, *hp;
    __nv_bfloat16 *eh, *el, *mlfh, *mlfl, *sh, *sl, *ah, *al, *mdh, *mdl, *wh, *wl;
    cudaGetSymbolAddress((void**)&pz,  g_pz);
    cudaGetSymbolAddress((void**)&ph,  g_ph);
    cudaGetSymbolAddress((void**)&pr,  g_pr);
    cudaGetSymbolAddress((void**)&pgt, g_pgt);
    cudaGetSymbolAddress((void**)&mlf, g_mlf);
    cudaGetSymbolAddress((void**)&rur, g_rur);
    cudaGetSymbolAddress((void**)&m,   g_m);
    cudaGetSymbolAddress((void**)&rm,  g_rm);
    cudaGetSymbolAddress((void**)&zp,  g_zp);
    cudaGetSymbolAddress((void**)&hp,  g_hp);
    cudaGetSymbolAddress((void**)&eh,  g_eh);
    cudaGetSymbolAddress((void**)&el,  g_el);
    cudaGetSymbolAddress((void**)&mlfh, g_mlfh);
    cudaGetSymbolAddress((void**)&mlfl, g_mlfl);
    cudaGetSymbolAddress((void**)&sh,  g_sh);
    cudaGetSymbolAddress((void**)&sl,  g_sl);
    cudaGetSymbolAddress((void**)&ah,  g_ah);
    cudaGetSymbolAddress((void**)&al,  g_al);
    cudaGetSymbolAddress((void**)&mdh, g_mdh);
    cudaGetSymbolAddress((void**)&mdl, g_mdl);
    cudaGetSymbolAddress((void**)&wh,  g_wh);
    cudaGetSymbolAddress((void**)&wl,  g_wl);

    cudaFuncSetAttribute(tc_vocab, cudaFuncAttributeMaxDynamicSharedMemorySize, SMEMB);
    cudaFuncSetAttribute(tc_rur,   cudaFuncAttributeMaxDynamicSharedMemorySize, SMEMB);
    cudaFuncSetAttribute(tc_zh,    cudaFuncAttributeMaxDynamicSharedMemorySize, SMEMB);
    cudaFuncSetAttribute(tc_ur,    cudaFuncAttributeMaxDynamicSharedMemorySize, SMEMB);
    cudaFuncSetAttribute(tc_fin,   cudaFuncAttributeMaxDynamicSharedMemorySize, SMEMB);

    const int NX = (HD + BN - 1) / BN;   // 8
    auto yb = [](int M) { return (M + BM - 1) / BM; };
    auto gb = [](int n) { return (n + 255) / 256; };

    // 0) preconvert weights + emb split
    preconv_k<<<gb(8 * HD * HDP / 2), 256>>>(Wz, Wh, Wr, Ur, Wg, wh, wl);
    esplit_k<<<gb(NV * HDP / 2), 256>>>(emb, eh, el);
    // 1) vocab tables
    tc_vocab<<<dim3(NX, yb(NV), 4), 256, SMEMB>>>(eh, el, wh, wl,
                                                  bz, bh, bU, bg, pz, ph, pr, pgt);
    // 2) leaf message table + its Ur image
    mleaf_k<<<gb(NV * HDP / 2), 256>>>(pz, ph, mlf, mlfh, mlfl);
    tc_rur<<<dim3(NX, yb(NV)), 256, SMEMB>>>(mlfh, mlfl, wh, wl, rur);
    // 3) all leaves
    leaf2_k<<<gb(NB * 16 * (HD / 2)), 256>>>(wid, mlf, rur, pr, m, rm);

    // 4) interior levels
    const int LO[4] = {15, 7, 3, 1};
    const int LG[4] = { 0, 3, 2, 1};
    for (int L = 0; L < 4; L++) {
        int lo = LO[L], lg = LG[L];
        int M = NB << lg;
        sumsplit_k<<<gb(M * HDP / 2), 256>>>(m, rm, sh, sl, ah, al, lo, lg, M, 1);
        tc_zh<<<dim3(NX, yb(M), 2), 256, SMEMB>>>(sh, sl, ah, al, wh, wl, zp, hp, M);
        mnew_k<<<gb(M * HDP / 2), 256>>>(wid, pz, ph, zp, hp, m, mdh, mdl, lo, lg, M);
        if (L < 3)
            tc_ur<<<dim3(NX, yb(M)), 256, SMEMB>>>(mdh, mdl, wh, wl,
                                                   rm, M, lo, lg, wid, pr, m);
    }

    // 5) final
    sumsplit_k<<<gb(NB * HDP / 2), 256>>>(m, rm, sh, sl, ah, al, 0, 0, NB, 0);
    tc_fin<<<dim3(NX, yb(NB)), 256, SMEMB>>>(sh, sl, wh, wl, out, wid, pgt);
}

// round 11
// speedup vs baseline: 2.1285x; 1.0242x over previous
#include <cuda_runtime.h>
#include <cuda_bf16.h>
#include <math.h>
#include <cstdint>

#define HD 450
#define HDP 464
#define NTREE 32
#define NB 1024
#define NNODE (NB*NTREE)
#define NV 780

// ---------------- scratch (static device memory) ----------------
__device__ float g_pz [NV*HD];
__device__ float g_ph [NV*HD];
__device__ float g_pr [NV*HD];
__device__ float g_pgt[NV*HD];
__device__ float g_mlf[NV*HD];
__device__ float g_rur[NV*HD];
__device__ float g_m  [NNODE*HD];   // interior nodes only
__device__ float g_rm [NNODE*HD];   // interior nodes only
__device__ float g_zp [NB*8*HD];
__device__ float g_hp [NB*8*HD];
// bf16 hi/lo split activations (dense rows, stride HDP, zero-padded)
__device__ __nv_bfloat16 g_eh  [NV*HDP],   g_el  [NV*HDP];
__device__ __nv_bfloat16 g_mlfh[NV*HDP],   g_mlfl[NV*HDP];
__device__ __nv_bfloat16 g_sh  [NB*8*HDP], g_sl  [NB*8*HDP];
__device__ __nv_bfloat16 g_ah  [NB*8*HDP], g_al  [NB*8*HDP];
__device__ __nv_bfloat16 g_mdh [NB*8*HDP], g_mdl [NB*8*HDP];
__device__ __nv_bfloat16 g_wh  [8*HD*HDP], g_wl  [8*HD*HDP];
// slots: 0 Wz_top, 1 Wz_bot, 2 Wh_top, 3 Wh_bot, 4 Wr, 5 Ur, 6 Wg_top, 7 Wg_bot

// ================= helpers =================
constexpr int BM = 128, BN = 64, BK = 64;
constexpr int NCHK = 8;
constexpr int ASTR = 72;
constexpr int BSTR = 72;
constexpr int STG  = 2*BM*ASTR + 2*BK*BSTR;   // 27648 elems/stage
constexpr int SMEMB = 2 * STG * 2;            // 110592 B

__device__ __forceinline__ void ldm_x4(uint32_t* r, uint32_t addr) {
    asm volatile("ldmatrix.sync.aligned.m8n8.x4.shared.b16 {%0,%1,%2,%3}, [%4];"
                 : "=r"(r[0]), "=r"(r[1]), "=r"(r[2]), "=r"(r[3]) : "r"(addr));
}
__device__ __forceinline__ void ldm_x2t(uint32_t* r, uint32_t addr) {
    asm volatile("ldmatrix.sync.aligned.m8n8.x2.trans.shared.b16 {%0,%1}, [%2];"
                 : "=r"(r[0]), "=r"(r[1]) : "r"(addr));
}
__device__ __forceinline__ void mma_bf16(float* c, const uint32_t* a, const uint32_t* b) {
    asm volatile("mma.sync.aligned.m16n8k16.row.col.f32.bf16.bf16.f32 "
                 "{%0,%1,%2,%3}, {%4,%5,%6,%7}, {%8,%9}, {%0,%1,%2,%3};"
                 : "+f"(c[0]), "+f"(c[1]), "+f"(c[2]), "+f"(c[3])
                 : "r"(a[0]), "r"(a[1]), "r"(a[2]), "r"(a[3]), "r"(b[0]), "r"(b[1]));
}
__device__ __forceinline__ void cp16(uint32_t smem, const void* g) {
    asm volatile("cp.async.cg.shared.global [%0], [%1], 16;" :: "r"(smem), "l"(g));
}
#define CP_COMMIT() asm volatile("cp.async.commit_group;")
#define CP_WAIT1()  asm volatile("cp.async.wait_group 1;" ::: "memory")

__device__ __forceinline__ void split2u(float2 v, uint32_t& hi, uint32_t& lo) {
    __nv_bfloat162 h = __floats2bfloat162_rn(v.x, v.y);
    __nv_bfloat162 l = __floats2bfloat162_rn(v.x - __bfloat162float(h.x),
                                             v.y - __bfloat162float(h.y));
    hi = *(uint32_t*)&h;
    lo = *(uint32_t*)&l;
}
__device__ __forceinline__ float sigf(float x) { return 1.f / (1.f + expf(-x)); }

// ================= GEMM body (unchanged, proven) =================
template<int EPI>
__device__ __forceinline__ void gemm_body(
    const __nv_bfloat16* __restrict__ Agh, const __nv_bfloat16* __restrict__ Agl,
    const __nv_bfloat16* __restrict__ Bgh, const __nv_bfloat16* __restrict__ Bgl,
    const float* __restrict__ bias, float* __restrict__ C,
    int M, int lo, int lg,
    const int* __restrict__ wid, const float* __restrict__ ptab,
    const float* __restrict__ pr, const float* __restrict__ msrc)
{
    extern __shared__ __align__(16) __nv_bfloat16 smp[];
    const int tid = threadIdx.x;
    const int lane = tid & 31, wrp = tid >> 5;
    const int wm = wrp & 3, wn = wrp >> 2;
    const int n0 = blockIdx.x * BN, m0 = blockIdx.y * BM;

    float acc[2][4][4] = {};

    const int q = lane >> 3, r8 = lane & 7;
    const int arow_off = (q & 1) * 8 + r8;
    const int acol_off = (q >> 1) * 8;
    const int l16 = lane & 15;
    const int bk_off = (l16 >> 3) * 8 + (l16 & 7);

    auto fill = [&](int s, int c) {
        __nv_bfloat16* Ah = smp + s * STG;
        __nv_bfloat16* Al = Ah + BM * ASTR;
        __nv_bfloat16* Bh = Al + BM * ASTR;
        __nv_bfloat16* Bl = Bh + BK * BSTR;
#pragma unroll
        for (int i = 0; i < 4; i++) {
            int idx = tid + i * 256;
            int row = idx >> 3, seg = idx & 7;
            int k = c * BK + seg * 8;
            int arow = m0 + row;
            __nv_bfloat16* dh = Ah + row * ASTR + seg * 8;
            __nv_bfloat16* dl = Al + row * ASTR + seg * 8;
            if (arow < M && k <= HDP - 8) {
                size_t gofs = (size_t)arow * HDP + k;
                cp16((uint32_t)__cvta_generic_to_shared(dh), Agh + gofs);
                cp16((uint32_t)__cvta_generic_to_shared(dl), Agl + gofs);
            } else {
                uint4 z = make_uint4(0, 0, 0, 0);
                *(uint4*)dh = z;
                *(uint4*)dl = z;
            }
        }
#pragma unroll
        for (int i = 0; i < 2; i++) {
            int idx = tid + i * 256;
            int kk = idx >> 3, seg = idx & 7;
            int k = c * BK + kk;
            __nv_bfloat16* dh = Bh + kk * BSTR + seg * 8;
            __nv_bfloat16* dl = Bl + kk * BSTR + seg * 8;
            if (k < HD) {
                size_t gofs = (size_t)k * HDP + n0 + seg * 8;
                cp16((uint32_t)__cvta_generic_to_shared(dh), Bgh + gofs);
                cp16((uint32_t)__cvta_generic_to_shared(dl), Bgl + gofs);
            } else {
                uint4 z = make_uint4(0, 0, 0, 0);
                *(uint4*)dh = z;
                *(uint4*)dl = z;
            }
        }
    };

    fill(0, 0);
    CP_COMMIT();
    for (int c = 0; c < NCHK; c++) {
        int st = c & 1;
        if (c + 1 < NCHK) fill(st ^ 1, c + 1);
        CP_COMMIT();
        CP_WAIT1();
        __syncthreads();

        const uint32_t sAh = (uint32_t)__cvta_generic_to_shared(smp + st * STG);
        const uint32_t sAl = sAh + BM * ASTR * 2;
        const uint32_t sBh = sAl + BM * ASTR * 2;
        const uint32_t sBl = sBh + BK * BSTR * 2;
#pragma unroll
        for (int ks = 0; ks < 4; ks++) {
            uint32_t ah[2][4], al[2][4], bh[4][2], bl[4][2];
#pragma unroll
            for (int mf = 0; mf < 2; mf++) {
                int row = wm * 32 + mf * 16 + arow_off;
                int col = ks * 16 + acol_off;
                uint32_t off = (uint32_t)(row * ASTR + col) * 2;
                ldm_x4(ah[mf], sAh + off);
                ldm_x4(al[mf], sAl + off);
            }
#pragma unroll
            for (int nf = 0; nf < 4; nf++) {
                int krow = ks * 16 + bk_off;
                uint32_t off = (uint32_t)(krow * BSTR + wn * 32 + nf * 8) * 2;
                ldm_x2t(bh[nf], sBh + off);
                ldm_x2t(bl[nf], sBl + off);
            }
#pragma unroll
            for (int mf = 0; mf < 2; mf++)
#pragma unroll
                for (int nf = 0; nf < 4; nf++) {
                    mma_bf16(acc[mf][nf], ah[mf], bh[nf]);
                    mma_bf16(acc[mf][nf], ah[mf], bl[nf]);
                    mma_bf16(acc[mf][nf], al[mf], bh[nf]);
                }
        }
        __syncthreads();
    }

    const int gr = lane >> 2, gc = (lane & 3) * 2;
#pragma unroll
    for (int mf = 0; mf < 2; mf++) {
#pragma unroll
        for (int h = 0; h < 2; h++) {
            int arow = m0 + wm * 32 + mf * 16 + h * 8 + gr;
            if (arow >= M) continue;
            int g = 0, wp = 0, w0 = 0;
            if constexpr (EPI == 3) {
                int t = arow >> lg, ci = lo + (arow & ((1 << lg) - 1));
                g  = t * NTREE + ci;
                wp = wid[t * NTREE + ((ci - 1) >> 1)];
            } else if constexpr (EPI == 4) {
                w0 = wid[arow * NTREE];
            }
#pragma unroll
            for (int nf = 0; nf < 4; nf++) {
                int j = n0 + wn * 32 + nf * 8 + gc;
                if (j >= HD) continue;
                float vx = acc[mf][nf][h * 2];
                float vy = acc[mf][nf][h * 2 + 1];
                if constexpr (EPI == 0) {
                    *(float2*)&C[arow * HD + j] = make_float2(vx, vy);
                } else if constexpr (EPI == 1) {
                    float2 b = *(const float2*)&bias[j];
                    *(float2*)&C[arow * HD + j] = make_float2(vx + b.x, vy + b.y);
                } else if constexpr (EPI == 3) {
                    float2 pv = *(const float2*)&pr[wp * HD + j];
                    float2 mv = *(const float2*)&msrc[g * HD + j];
                    float rx = sigf(pv.x + vx);
                    float ry = sigf(pv.y + vy);
                    *(float2*)&C[g * HD + j] = make_float2(rx * mv.x, ry * mv.y);
                } else { // EPI == 4
                    float2 pv = *(const float2*)&ptab[w0 * HD + j];
                    *(float2*)&C[arow * HD + j] =
                        make_float2(fmaxf(pv.x + vx, 0.f), fmaxf(pv.y + vy, 0.f));
                }
            }
        }
    }
}

// ================= GEMM wrappers =================
__global__ __launch_bounds__(256) void tc_vocab(
    const __nv_bfloat16* eh, const __nv_bfloat16* el,
    const __nv_bfloat16* wh, const __nv_bfloat16* wl,
    const float* bz, const float* bh_, const float* bU, const float* bg,
    float* pz, float* ph_, float* pr, float* pgt)
{
    const int SZ = HD * HDP;
    const float* b; float* C; int slot;
    switch (blockIdx.z) {
        case 0:  slot = 0; b = bz;  C = pz;  break;
        case 1:  slot = 2; b = bh_; C = ph_; break;
        case 2:  slot = 4; b = bU;  C = pr;  break;
        default: slot = 6; b = bg;  C = pgt; break;
    }
    gemm_body<1>(eh, el, wh + slot * SZ, wl + slot * SZ, b, C,
                 NV, 0, 0, nullptr, nullptr, nullptr, nullptr);
}

__global__ __launch_bounds__(256) void tc_rur(
    const __nv_bfloat16* mlfh, const __nv_bfloat16* mlfl,
    const __nv_bfloat16* wh, const __nv_bfloat16* wl, float* rur)
{
    const int SZ = HD * HDP;
    gemm_body<0>(mlfh, mlfl, wh + 5 * SZ, wl + 5 * SZ, nullptr, rur,
                 NV, 0, 0, nullptr, nullptr, nullptr, nullptr);
}

__global__ __launch_bounds__(256) void tc_zh(
    const __nv_bfloat16* sh, const __nv_bfloat16* sl,
    const __nv_bfloat16* ah, const __nv_bfloat16* al,
    const __nv_bfloat16* wh, const __nv_bfloat16* wl,
    float* zp, float* hp, int M)
{
    const int SZ = HD * HDP;
    if (blockIdx.z == 0)
        gemm_body<0>(sh, sl, wh + 1 * SZ, wl + 1 * SZ, nullptr, zp,
                     M, 0, 0, nullptr, nullptr, nullptr, nullptr);
    else
        gemm_body<0>(ah, al, wh + 3 * SZ, wl + 3 * SZ, nullptr, hp,
                     M, 0, 0, nullptr, nullptr, nullptr, nullptr);
}

__global__ __launch_bounds__(256) void tc_ur(
    const __nv_bfloat16* mdh, const __nv_bfloat16* mdl,
    const __nv_bfloat16* wh, const __nv_bfloat16* wl,
    float* rm, int M, int lo, int lg,
    const int* wid, const float* pr, const float* msrc)
{
    const int SZ = HD * HDP;
    gemm_body<3>(mdh, mdl, wh + 5 * SZ, wl + 5 * SZ, nullptr, rm,
                 M, lo, lg, wid, nullptr, pr, msrc);
}

__global__ __launch_bounds__(256) void tc_fin(
    const __nv_bfloat16* sh, const __nv_bfloat16* sl,
    const __nv_bfloat16* wh, const __nv_bfloat16* wl,
    float* out, const int* wid, const float* pgt)
{
    const int SZ = HD * HDP;
    gemm_body<4>(sh, sl, wh + 7 * SZ, wl + 7 * SZ, nullptr, out,
                 NB, 0, 0, wid, pgt, nullptr, nullptr);
}

// ================= producers =================
__global__ void preconv_k(const float* __restrict__ Wz, const float* __restrict__ Wh,
                          const float* __restrict__ Wr, const float* __restrict__ Ur,
                          const float* __restrict__ Wg,
                          __nv_bfloat16* __restrict__ wh, __nv_bfloat16* __restrict__ wl)
{
    int idx = blockIdx.x * blockDim.x + threadIdx.x;
    const int SZ2 = HD * HDP / 2;
    if (idx >= 8 * SZ2) return;
    int slot = idx / SZ2, off = idx - slot * SZ2;
    int k = off / (HDP / 2), j = (off - k * (HDP / 2)) * 2;
    float2 v = make_float2(0.f, 0.f);
    if (j < HD) {
        int src = k * HD + j;
        const int WSZ = HD * HD;
        switch (slot) {
            case 0:  v = *(const float2*)&Wz[src];       break;
            case 1:  v = *(const float2*)&Wz[WSZ + src]; break;
            case 2:  v = *(const float2*)&Wh[src];       break;
            case 3:  v = *(const float2*)&Wh[WSZ + src]; break;
            case 4:  v = *(const float2*)&Wr[src];       break;
            case 5:  v = *(const float2*)&Ur[src];       break;
            case 6:  v = *(const float2*)&Wg[src];       break;
            default: v = *(const float2*)&Wg[WSZ + src]; break;
        }
    }
    uint32_t hi, lo;
    split2u(v, hi, lo);
    int d = slot * HD * HDP + k * HDP + j;
    *(uint32_t*)&wh[d] = hi;
    *(uint32_t*)&wl[d] = lo;
}

__global__ void esplit_k(const float* __restrict__ emb,
                         __nv_bfloat16* __restrict__ eh, __nv_bfloat16* __restrict__ el)
{
    int idx = blockIdx.x * blockDim.x + threadIdx.x;
    if (idx >= NV * HDP / 2) return;
    int row = idx / (HDP / 2), j = (idx - row * (HDP / 2)) * 2;
    float2 v = (j < HD) ? *(const float2*)&emb[row * HD + j] : make_float2(0.f, 0.f);
    uint32_t hi, lo;
    split2u(v, hi, lo);
    *(uint32_t*)&eh[row * HDP + j] = hi;
    *(uint32_t*)&el[row * HDP + j] = lo;
}

__global__ void mleaf_k(const float* __restrict__ pz, const float* __restrict__ ph,
                        float* __restrict__ mlf,
                        __nv_bfloat16* __restrict__ mlfh, __nv_bfloat16* __restrict__ mlfl)
{
    int idx = blockIdx.x * blockDim.x + threadIdx.x;
    if (idx >= NV * HDP / 2) return;
    int row = idx / (HDP / 2), j = (idx - row * (HDP / 2)) * 2;
    float2 v = make_float2(0.f, 0.f);
    if (j < HD) {
        int s = row * HD + j;
        float2 a = *(const float2*)&pz[s];
        float2 b = *(const float2*)&ph[s];
        v.x = tanhf(b.x) * sigf(a.x);
        v.y = tanhf(b.y) * sigf(a.y);
        *(float2*)&mlf[s] = v;
    }
    uint32_t hi, lo;
    split2u(v, hi, lo);
    *(uint32_t*)&mlfh[row * HDP + j] = hi;
    *(uint32_t*)&mlfl[row * HDP + j] = lo;
}

// s/arm for node 15 (children: only node 31, a leaf) -> rows t
__global__ void s0_k(const int* __restrict__ wid,
                     const float* __restrict__ pr, const float* __restrict__ rur,
                     const float* __restrict__ mlf,
                     __nv_bfloat16* __restrict__ sh, __nv_bfloat16* __restrict__ sl,
                     __nv_bfloat16* __restrict__ ah, __nv_bfloat16* __restrict__ al)
{
    int idx = blockIdx.x * blockDim.x + threadIdx.x;
    if (idx >= NB * (HDP / 2)) return;
    int t = idx / (HDP / 2), j = (idx - t * (HDP / 2)) * 2;
    float2 s = make_float2(0.f, 0.f), a = s;
    if (j < HD) {
        int w15 = wid[t * NTREE + 15];
        int w31 = wid[t * NTREE + 31];
        s = *(const float2*)&mlf[w31 * HD + j];
        float2 ru = *(const float2*)&rur[w31 * HD + j];
        float2 pv = *(const float2*)&pr[w15 * HD + j];
        a = make_float2(sigf(pv.x + ru.x) * s.x, sigf(pv.y + ru.y) * s.y);
    }
    uint32_t hi, lo;
    int d = t * HDP + j;
    split2u(s, hi, lo); *(uint32_t*)&sh[d] = hi; *(uint32_t*)&sl[d] = lo;
    split2u(a, hi, lo); *(uint32_t*)&ah[d] = hi; *(uint32_t*)&al[d] = lo;
}

// prep: compute m_new for both children of each parent in [PLO, PLO+PCNT),
// write m (fp32) + mdh/mdl (child-level rows), and parent s -> sh/sl.
// Interior child level: nodes [CLO, CLO+CCNT), zp/hp row = t*CCNT + (c-CLO).
template<int PLO, int PCNT, int CLO, int CCNT, int WMD>
__global__ void prep_k(const int* __restrict__ wid,
                       const float* __restrict__ pz, const float* __restrict__ ph,
                       const float* __restrict__ zp, const float* __restrict__ hp,
                       const float* __restrict__ mlf,
                       float* __restrict__ m,
                       __nv_bfloat16* __restrict__ mdh, __nv_bfloat16* __restrict__ mdl,
                       __nv_bfloat16* __restrict__ sh, __nv_bfloat16* __restrict__ sl)
{
    int idx = blockIdx.x * blockDim.x + threadIdx.x;
    if (idx >= NB * PCNT * (HDP / 2)) return;
    int row = idx / (HDP / 2), j = (idx - row * (HDP / 2)) * 2;
    int t = row / PCNT;
    int p = PLO + (row - t * PCNT);
    float2 msum = make_float2(0.f, 0.f);
    if (j < HD) {
#pragma unroll
        for (int ch = 0; ch < 2; ch++) {
            int c = 2 * p + 1 + ch;
            float2 mc;
            if (c >= 16) {
                int w = wid[t * NTREE + c];
                mc = *(const float2*)&mlf[w * HD + j];
            } else {
                int crow = t * CCNT + (c - CLO);
                int w = wid[t * NTREE + c];
                float2 pzv = *(const float2*)&pz[w * HD + j];
                float2 phv = *(const float2*)&ph[w * HD + j];
                float2 zpv = *(const float2*)&zp[crow * HD + j];
                float2 hpv = *(const float2*)&hp[crow * HD + j];
                // s of child = sum over grandchildren
                int gc1 = 2 * c + 1, gc2 = 2 * c + 2;
                float2 s;
                if (gc1 < 16)  s = *(const float2*)&m[(t * NTREE + gc1) * HD + j];
                else           s = *(const float2*)&mlf[wid[t * NTREE + gc1] * HD + j];
                if (gc2 < NTREE) {
                    float2 s2;
                    if (gc2 < 16) s2 = *(const float2*)&m[(t * NTREE + gc2) * HD + j];
                    else          s2 = *(const float2*)&mlf[wid[t * NTREE + gc2] * HD + j];
                    s.x += s2.x; s.y += s2.y;
                }
                float zx = sigf(pzv.x + zpv.x);
                float zy = sigf(pzv.y + zpv.y);
                mc.x = (1.f - zx) * s.x + zx * tanhf(phv.x + hpv.x);
                mc.y = (1.f - zy) * s.y + zy * tanhf(phv.y + hpv.y);
                *(float2*)&m[(t * NTREE + c) * HD + j] = mc;
                if (WMD) {
                    uint32_t hi, lo;
                    split2u(mc, hi, lo);
                    *(uint32_t*)&mdh[crow * HDP + j] = hi;
                    *(uint32_t*)&mdl[crow * HDP + j] = lo;
                }
            }
            msum.x += mc.x; msum.y += mc.y;
        }
    } else if (WMD) {
        // zero mdh/mdl padding for interior child rows
#pragma unroll
        for (int ch = 0; ch < 2; ch++) {
            int c = 2 * p + 1 + ch;
            if (c < 16) {
                int crow = t * CCNT + (c - CLO);
                *(uint32_t*)&mdh[crow * HDP + j] = 0;
                *(uint32_t*)&mdl[crow * HDP + j] = 0;
            }
        }
    }
    uint32_t hi, lo;
    split2u(msum, hi, lo);
    *(uint32_t*)&sh[row * HDP + j] = hi;
    *(uint32_t*)&sl[row * HDP + j] = lo;
}

// arm for nodes of level [LO, LO+CNT): sum children's rm (leaf rm from tables)
template<int LO, int CNT>
__global__ void armsplit_k(const int* __restrict__ wid,
                           const float* __restrict__ pr, const float* __restrict__ rur,
                           const float* __restrict__ mlf, const float* __restrict__ rm,
                           __nv_bfloat16* __restrict__ ah, __nv_bfloat16* __restrict__ al)
{
    int idx = blockIdx.x * blockDim.x + threadIdx.x;
    if (idx >= NB * CNT * (HDP / 2)) return;
    int row = idx / (HDP / 2), j = (idx - row * (HDP / 2)) * 2;
    int t = row / CNT;
    int n = LO + (row - t * CNT);
    float2 a = make_float2(0.f, 0.f);
    if (j < HD) {
        int wp = wid[t * NTREE + n];
#pragma unroll
        for (int ch = 0; ch < 2; ch++) {
            int c = 2 * n + 1 + ch;
            if (c < 16) {
                float2 rv = *(const float2*)&rm[(t * NTREE + c) * HD + j];
                a.x += rv.x; a.y += rv.y;
            } else {
                int w = wid[t * NTREE + c];
                float2 ru = *(const float2*)&rur[w * HD + j];
                float2 pv = *(const float2*)&pr[wp * HD + j];
                float2 mv = *(const float2*)&mlf[w * HD + j];
                a.x += sigf(pv.x + ru.x) * mv.x;
                a.y += sigf(pv.y + ru.y) * mv.y;
            }
        }
    }
    uint32_t hi, lo;
    split2u(a, hi, lo);
    *(uint32_t*)&ah[row * HDP + j] = hi;
    *(uint32_t*)&al[row * HDP + j] = lo;
}

// ================= launch =================
extern "C" void kernel_launch(void* const* d_in, const int* in_sizes, int n_in,
                              void* d_out, int out_size)
{
    const int*   wid = (const int*)  d_in[0];
    const float* emb = (const float*)d_in[1];
    const float* Wz  = (const float*)d_in[2];
    const float* bz  = (const float*)d_in[3];
    const float* Wr  = (const float*)d_in[4];
    const float* Ur  = (const float*)d_in[5];
    const float* bU  = (const float*)d_in[6];
    const float* Wh  = (const float*)d_in[7];
    const float* bh  = (const float*)d_in[8];
    const float* Wg  = (const float*)d_in[9];
    const float* bg  = (const float*)d_in[10];
    float* out = (float*)d_out;

    float *pz, *ph, *pr, *pgt, *mlf, *rur, *m, *rm, *zp, *hp;
    __nv_bfloat16 *eh, *el, *mlfh, *mlfl, *sh, *sl, *ah, *al, *mdh, *mdl, *wh, *wl;
    cudaGetSymbolAddress((void**)&pz,  g_pz);
    cudaGetSymbolAddress((void**)&ph,  g_ph);
    cudaGetSymbolAddress((void**)&pr,  g_pr);
    cudaGetSymbolAddress((void**)&pgt, g_pgt);
    cudaGetSymbolAddress((void**)&mlf, g_mlf);
    cudaGetSymbolAddress((void**)&rur, g_rur);
    cudaGetSymbolAddress((void**)&m,   g_m);
    cudaGetSymbolAddress((void**)&rm,  g_rm);
    cudaGetSymbolAddress((void**)&zp,  g_zp);
    cudaGetSymbolAddress((void**)&hp,  g_hp);
    cudaGetSymbolAddress((void**)&eh,  g_eh);
    cudaGetSymbolAddress((void**)&el,  g_el);
    cudaGetSymbolAddress((void**)&mlfh, g_mlfh);
    cudaGetSymbolAddress((void**)&mlfl, g_mlfl);
    cudaGetSymbolAddress((void**)&sh,  g_sh);
    cudaGetSymbolAddress((void**)&sl,  g_sl);
    cudaGetSymbolAddress((void**)&ah,  g_ah);
    cudaGetSymbolAddress((void**)&al,  g_al);
    cudaGetSymbolAddress((void**)&mdh, g_mdh);
    cudaGetSymbolAddress((void**)&mdl, g_mdl);
    cudaGetSymbolAddress((void**)&wh,  g_wh);
    cudaGetSymbolAddress((void**)&wl,  g_wl);

    cudaFuncSetAttribute(tc_vocab, cudaFuncAttributeMaxDynamicSharedMemorySize, SMEMB);
    cudaFuncSetAttribute(tc_rur,   cudaFuncAttributeMaxDynamicSharedMemorySize, SMEMB);
    cudaFuncSetAttribute(tc_zh,    cudaFuncAttributeMaxDynamicSharedMemorySize, SMEMB);
    cudaFuncSetAttribute(tc_ur,    cudaFuncAttributeMaxDynamicSharedMemorySize, SMEMB);
    cudaFuncSetAttribute(tc_fin,   cudaFuncAttributeMaxDynamicSharedMemorySize, SMEMB);

    const int NX = (HD + BN - 1) / BN;   // 8
    auto yb = [](int M) { return (M + BM - 1) / BM; };
    auto gb = [](int n) { return (n + 255) / 256; };

    // prelude
    preconv_k<<<gb(8 * HD * HDP / 2), 256>>>(Wz, Wh, Wr, Ur, Wg, wh, wl);
    esplit_k<<<gb(NV * HDP / 2), 256>>>(emb, eh, el);
    tc_vocab<<<dim3(NX, yb(NV), 4), 256, SMEMB>>>(eh, el, wh, wl,
                                                  bz, bh, bU, bg, pz, ph, pr, pgt);
    mleaf_k<<<gb(NV * HDP / 2), 256>>>(pz, ph, mlf, mlfh, mlfl);
    tc_rur<<<dim3(NX, yb(NV)), 256, SMEMB>>>(mlfh, mlfl, wh, wl, rur);

    // level 0 (node 15)
    s0_k<<<gb(NB * HDP / 2), 256>>>(wid, pr, rur, mlf, sh, sl, ah, al);
    tc_zh<<<dim3(NX, yb(NB), 2), 256, SMEMB>>>(sh, sl, ah, al, wh, wl, zp, hp, NB);
    // prep L1: parents 7..14, interior child level {15}
    prep_k<7, 8, 15, 1, 1><<<gb(NB * 8 * HDP / 2), 256>>>(wid, pz, ph, zp, hp, mlf,
                                                          m, mdh, mdl, sh, sl);
    tc_ur<<<dim3(NX, yb(NB)), 256, SMEMB>>>(mdh, mdl, wh, wl, rm, NB, 15, 0, wid, pr, m);
    armsplit_k<7, 8><<<gb(NB * 8 * HDP / 2), 256>>>(wid, pr, rur, mlf, rm, ah, al);
    tc_zh<<<dim3(NX, yb(NB * 8), 2), 256, SMEMB>>>(sh, sl, ah, al, wh, wl, zp, hp, NB * 8);
    // prep L2: parents 3..6, children 7..14
    prep_k<3, 4, 7, 8, 1><<<gb(NB * 4 * HDP / 2), 256>>>(wid, pz, ph, zp, hp, mlf,
                                                         m, mdh, mdl, sh, sl);
    tc_ur<<<dim3(NX, yb(NB * 8)), 256, SMEMB>>>(mdh, mdl, wh, wl, rm, NB * 8, 7, 3, wid, pr, m);
    armsplit_k<3, 4><<<gb(NB * 4 * HDP / 2), 256>>>(wid, pr, rur, mlf, rm, ah, al);
    tc_zh<<<dim3(NX, yb(NB * 4), 2), 256, SMEMB>>>(sh, sl, ah, al, wh, wl, zp, hp, NB * 4);
    // prep L3: parents 1..2, children 3..6
    prep_k<1, 2, 3, 4, 1><<<gb(NB * 2 * HDP / 2), 256>>>(wid, pz, ph, zp, hp, mlf,
                                                         m, mdh, mdl, sh, sl);
    tc_ur<<<dim3(NX, yb(NB * 4)), 256, SMEMB>>>(mdh, mdl, wh, wl, rm, NB * 4, 3, 2, wid, pr, m);
    armsplit_k<1, 2><<<gb(NB * 2 * HDP / 2), 256>>>(wid, pr, rur, mlf, rm, ah, al);
    tc_zh<<<dim3(NX, yb(NB * 2), 2), 256, SMEMB>>>(sh, sl, ah, al, wh, wl, zp, hp, NB * 2);
    // root: parent 0, children 1..2 -> s_root
    prep_k<0, 1, 1, 2, 0><<<gb(NB * HDP / 2), 256>>>(wid, pz, ph, zp, hp, mlf,
                                                     m, mdh, mdl, sh, sl);
    tc_fin<<<dim3(NX, yb(NB)), 256, SMEMB>>>(sh, sl, wh, wl, out, wid, pgt);
}

// round 13
// speedup vs baseline: 2.7349x; 1.2849x over previous
#include <cuda_runtime.h>
#include <cuda_fp16.h>
#include <math.h>
#include <cstdint>

#define HD 450
#define HDP 464
#define NTREE 32
#define NB 1024
#define NNODE (NB*NTREE)
#define NV 780

// ---------------- scratch (static device memory) ----------------
__device__ float g_pz [NV*HD];
__device__ float g_ph [NV*HD];
__device__ float g_pr [NV*HD];
__device__ float g_pgt[NV*HD];
__device__ float g_mlf[NV*HD];
__device__ float g_rur[NV*HD];
__device__ float g_m  [NNODE*HD];
__device__ float g_rm [NNODE*HD];
__device__ float g_zp [NB*8*HD];
__device__ float g_hp [NB*8*HD];
// fp16 activations (dense rows, stride HDP, zero-padded)
__device__ __half g_ef  [NV*HDP];     // emb
__device__ __half g_mlff[NV*HDP];     // leaf msg table
__device__ __half g_sf  [NB*8*HDP];   // child-sum s
__device__ __half g_af  [NB*8*HDP];   // child-sum arm
__device__ __half g_mdf [NB*8*HDP];   // m_new dense
// fp16 weights, SPLIT hi/lo (precomputed once)
__device__ __half g_wh  [8*HD*HDP];
__device__ __half g_wl  [8*HD*HDP];
// slots: 0 Wz_top, 1 Wz_bot, 2 Wh_top, 3 Wh_bot, 4 Wr, 5 Ur, 6 Wg_top, 7 Wg_bot

// ================= helpers =================
constexpr int BM = 128, BN = 64, BK = 64;
constexpr int NCHK = 8;
constexpr int ASTR = 72;
constexpr int BSTR = 72;
constexpr int STG  = BM*ASTR + 2*BK*BSTR;     // 18432 halfs/stage
constexpr int SMEMB = 2 * STG * 2;            // 73728 B (2 stages)

__device__ __forceinline__ void ldm_x4(uint32_t* r, uint32_t addr) {
    asm volatile("ldmatrix.sync.aligned.m8n8.x4.shared.b16 {%0,%1,%2,%3}, [%4];"
                 : "=r"(r[0]), "=r"(r[1]), "=r"(r[2]), "=r"(r[3]) : "r"(addr));
}
__device__ __forceinline__ void ldm_x2t(uint32_t* r, uint32_t addr) {
    asm volatile("ldmatrix.sync.aligned.m8n8.x2.trans.shared.b16 {%0,%1}, [%2];"
                 : "=r"(r[0]), "=r"(r[1]) : "r"(addr));
}
__device__ __forceinline__ void mma_fp16(float* c, const uint32_t* a, const uint32_t* b) {
    asm volatile("mma.sync.aligned.m16n8k16.row.col.f32.f16.f16.f32 "
                 "{%0,%1,%2,%3}, {%4,%5,%6,%7}, {%8,%9}, {%0,%1,%2,%3};"
                 : "+f"(c[0]), "+f"(c[1]), "+f"(c[2]), "+f"(c[3])
                 : "r"(a[0]), "r"(a[1]), "r"(a[2]), "r"(a[3]), "r"(b[0]), "r"(b[1]));
}
__device__ __forceinline__ void cp16(uint32_t smem, const void* g) {
    asm volatile("cp.async.cg.shared.global [%0], [%1], 16;" :: "r"(smem), "l"(g));
}
#define CP_COMMIT() asm volatile("cp.async.commit_group;")
#define CP_WAIT1()  asm volatile("cp.async.wait_group 1;" ::: "memory")

__device__ __forceinline__ uint32_t pack2h(float2 v) {
    __half2 h = __floats2half2_rn(v.x, v.y);
    return *(uint32_t*)&h;
}
__device__ __forceinline__ void split2h(float2 v, uint32_t& hi, uint32_t& lo) {
    __half2 h = __floats2half2_rn(v.x, v.y);
    float rx = v.x - __half2float(__low2half(h));
    float ry = v.y - __half2float(__high2half(h));
    __half2 l = __floats2half2_rn(rx, ry);
    hi = *(uint32_t*)&h;
    lo = *(uint32_t*)&l;
}
__device__ __forceinline__ float sigf(float x) { return 1.f / (1.f + expf(-x)); }

// ================= GEMM body: fp16 A plain, B hi/lo, 2-term =================
// C[M x 450] = A[M x 450] @ W[450 x 450]
// EPI: 0 plain; 1 +bias; 3 rm=sig(pr[wp]+acc)*msrc; 4 relu(ptab[w0]+acc)
template<int EPI>
__device__ __forceinline__ void gemm_body(
    const __half* __restrict__ Ag,
    const __half* __restrict__ Bgh, const __half* __restrict__ Bgl,
    const float* __restrict__ bias, float* __restrict__ C,
    int M, int lo, int lg,
    const int* __restrict__ wid, const float* __restrict__ ptab,
    const float* __restrict__ pr, const float* __restrict__ msrc)
{
    extern __shared__ __align__(16) __half smp[];
    const int tid = threadIdx.x;
    const int lane = tid & 31, wrp = tid >> 5;
    const int wm = wrp & 3, wn = wrp >> 2;
    const int n0 = blockIdx.x * BN, m0 = blockIdx.y * BM;

    float acc[2][4][4] = {};

    const int q = lane >> 3, r8 = lane & 7;
    const int arow_off = (q & 1) * 8 + r8;
    const int acol_off = (q >> 1) * 8;
    const int l16 = lane & 15;
    const int bk_off = (l16 >> 3) * 8 + (l16 & 7);

    auto fill = [&](int s, int c) {
        __half* Asm = smp + s * STG;
        __half* Bh  = Asm + BM * ASTR;
        __half* Bl  = Bh + BK * BSTR;
        // A: 128 rows x 8 segs (16B) = 1024 cp / 256 thr = 4 each
#pragma unroll
        for (int i = 0; i < 4; i++) {
            int idx = tid + i * 256;
            int row = idx >> 3, seg = idx & 7;
            int k = c * BK + seg * 8;
            int arow = m0 + row;
            __half* d = Asm + row * ASTR + seg * 8;
            if (arow < M && k <= HDP - 8) {
                cp16((uint32_t)__cvta_generic_to_shared(d), Ag + (size_t)arow * HDP + k);
            } else {
                *(uint4*)d = make_uint4(0, 0, 0, 0);
            }
        }
        // B: 64 k-rows x 8 segs, hi+lo; 2 iters x 256 thr x 2 cp
#pragma unroll
        for (int i = 0; i < 2; i++) {
            int idx = tid + i * 256;
            int kk = idx >> 3, seg = idx & 7;
            int k = c * BK + kk;
            int nj = n0 + seg * 8;
            __half* dh = Bh + kk * BSTR + seg * 8;
            __half* dl = Bl + kk * BSTR + seg * 8;
            if (k < HD && nj <= HDP - 8) {
                size_t gofs = (size_t)k * HDP + nj;
                cp16((uint32_t)__cvta_generic_to_shared(dh), Bgh + gofs);
                cp16((uint32_t)__cvta_generic_to_shared(dl), Bgl + gofs);
            } else {
                *(uint4*)dh = make_uint4(0, 0, 0, 0);
                *(uint4*)dl = make_uint4(0, 0, 0, 0);
            }
        }
    };

    fill(0, 0);
    CP_COMMIT();
    for (int c = 0; c < NCHK; c++) {
        int st = c & 1;
        if (c + 1 < NCHK) fill(st ^ 1, c + 1);
        CP_COMMIT();
        CP_WAIT1();
        __syncthreads();

        const uint32_t sA  = (uint32_t)__cvta_generic_to_shared(smp + st * STG);
        const uint32_t sBh = sA + BM * ASTR * 2;
        const uint32_t sBl = sBh + BK * BSTR * 2;
#pragma unroll
        for (int ks = 0; ks < 4; ks++) {
            uint32_t ah[2][4], bh[4][2], bl[4][2];
#pragma unroll
            for (int mf = 0; mf < 2; mf++) {
                int row = wm * 32 + mf * 16 + arow_off;
                int col = ks * 16 + acol_off;
                ldm_x4(ah[mf], sA + (uint32_t)(row * ASTR + col) * 2);
            }
#pragma unroll
            for (int nf = 0; nf < 4; nf++) {
                int krow = ks * 16 + bk_off;
                uint32_t off = (uint32_t)(krow * BSTR + wn * 32 + nf * 8) * 2;
                ldm_x2t(bh[nf], sBh + off);
                ldm_x2t(bl[nf], sBl + off);
            }
#pragma unroll
            for (int mf = 0; mf < 2; mf++)
#pragma unroll
                for (int nf = 0; nf < 4; nf++) {
                    mma_fp16(acc[mf][nf], ah[mf], bh[nf]);
                    mma_fp16(acc[mf][nf], ah[mf], bl[nf]);
                }
        }
        __syncthreads();
    }

    const int gr = lane >> 2, gc = (lane & 3) * 2;
#pragma unroll
    for (int mf = 0; mf < 2; mf++) {
#pragma unroll
        for (int h = 0; h < 2; h++) {
            int arow = m0 + wm * 32 + mf * 16 + h * 8 + gr;
            if (arow >= M) continue;
            int g = 0, wp = 0, w0 = 0;
            if constexpr (EPI == 3) {
                int t = arow >> lg, ci = lo + (arow & ((1 << lg) - 1));
                g  = t * NTREE + ci;
                wp = wid[t * NTREE + ((ci - 1) >> 1)];
            } else if constexpr (EPI == 4) {
                w0 = wid[arow * NTREE];
            }
#pragma unroll
            for (int nf = 0; nf < 4; nf++) {
                int j = n0 + wn * 32 + nf * 8 + gc;
                if (j >= HD) continue;
                float vx = acc[mf][nf][h * 2];
                float vy = acc[mf][nf][h * 2 + 1];
                if constexpr (EPI == 0) {
                    *(float2*)&C[arow * HD + j] = make_float2(vx, vy);
                } else if constexpr (EPI == 1) {
                    float2 b = *(const float2*)&bias[j];
                    *(float2*)&C[arow * HD + j] = make_float2(vx + b.x, vy + b.y);
                } else if constexpr (EPI == 3) {
                    float2 pv = *(const float2*)&pr[wp * HD + j];
                    float2 mv = *(const float2*)&msrc[g * HD + j];
                    float rx = sigf(pv.x + vx);
                    float ry = sigf(pv.y + vy);
                    *(float2*)&C[g * HD + j] = make_float2(rx * mv.x, ry * mv.y);
                } else { // EPI == 4
                    float2 pv = *(const float2*)&ptab[w0 * HD + j];
                    *(float2*)&C[arow * HD + j] =
                        make_float2(fmaxf(pv.x + vx, 0.f), fmaxf(pv.y + vy, 0.f));
                }
            }
        }
    }
}

// ================= GEMM wrappers =================
__global__ __launch_bounds__(256) void tc_vocab(
    const __half* ef, const __half* wh, const __half* wl,
    const float* bz, const float* bh_, const float* bU, const float* bg,
    float* pz, float* ph_, float* pr, float* pgt)
{
    const int SZ = HD * HDP;
    const float* b; float* C; int slot;
    switch (blockIdx.z) {
        case 0:  slot = 0; b = bz;  C = pz;  break;
        case 1:  slot = 2; b = bh_; C = ph_; break;
        case 2:  slot = 4; b = bU;  C = pr;  break;
        default: slot = 6; b = bg;  C = pgt; break;
    }
    gemm_body<1>(ef, wh + slot * SZ, wl + slot * SZ, b, C,
                 NV, 0, 0, nullptr, nullptr, nullptr, nullptr);
}

__global__ __launch_bounds__(256) void tc_rur(
    const __half* mlff, const __half* wh, const __half* wl, float* rur)
{
    const int SZ = HD * HDP;
    gemm_body<0>(mlff, wh + 5 * SZ, wl + 5 * SZ, nullptr, rur,
                 NV, 0, 0, nullptr, nullptr, nullptr, nullptr);
}

__global__ __launch_bounds__(256) void tc_zh(
    const __half* sf, const __half* af,
    const __half* wh, const __half* wl,
    float* zp, float* hp, int M)
{
    const int SZ = HD * HDP;
    if (blockIdx.z == 0)
        gemm_body<0>(sf, wh + 1 * SZ, wl + 1 * SZ, nullptr, zp,
                     M, 0, 0, nullptr, nullptr, nullptr, nullptr);
    else
        gemm_body<0>(af, wh + 3 * SZ, wl + 3 * SZ, nullptr, hp,
                     M, 0, 0, nullptr, nullptr, nullptr, nullptr);
}

__global__ __launch_bounds__(256) void tc_ur(
    const __half* mdf, const __half* wh, const __half* wl,
    float* rm, int M, int lo, int lg,
    const int* wid, const float* pr, const float* msrc)
{
    const int SZ = HD * HDP;
    gemm_body<3>(mdf, wh + 5 * SZ, wl + 5 * SZ, nullptr, rm,
                 M, lo, lg, wid, nullptr, pr, msrc);
}

__global__ __launch_bounds__(256) void tc_fin(
    const __half* sf, const __half* wh, const __half* wl,
    float* out, const int* wid, const float* pgt)
{
    const int SZ = HD * HDP;
    gemm_body<4>(sf, wh + 7 * SZ, wl + 7 * SZ, nullptr, out,
                 NB, 0, 0, wid, pgt, nullptr, nullptr);
}

// ================= producers =================
__global__ void preconv_k(const float* __restrict__ Wz, const float* __restrict__ Wh,
                          const float* __restrict__ Wr, const float* __restrict__ Ur,
                          const float* __restrict__ Wg,
                          __half* __restrict__ wh, __half* __restrict__ wl)
{
    int idx = blockIdx.x * blockDim.x + threadIdx.x;
    const int SZ2 = HD * HDP / 2;
    if (idx >= 8 * SZ2) return;
    int slot = idx / SZ2, off = idx - slot * SZ2;
    int k = off / (HDP / 2), j = (off - k * (HDP / 2)) * 2;
    float2 v = make_float2(0.f, 0.f);
    if (j < HD) {
        int src = k * HD + j;
        const int WSZ = HD * HD;
        switch (slot) {
            case 0:  v = *(const float2*)&Wz[src];       break;
            case 1:  v = *(const float2*)&Wz[WSZ + src]; break;
            case 2:  v = *(const float2*)&Wh[src];       break;
            case 3:  v = *(const float2*)&Wh[WSZ + src]; break;
            case 4:  v = *(const float2*)&Wr[src];       break;
            case 5:  v = *(const float2*)&Ur[src];       break;
            case 6:  v = *(const float2*)&Wg[src];       break;
            default: v = *(const float2*)&Wg[WSZ + src]; break;
        }
    }
    uint32_t hi, lo;
    split2h(v, hi, lo);
    int d = slot * HD * HDP + k * HDP + j;
    *(uint32_t*)&wh[d] = hi;
    *(uint32_t*)&wl[d] = lo;
}

__global__ void esplit_k(const float* __restrict__ emb, __half* __restrict__ ef)
{
    int idx = blockIdx.x * blockDim.x + threadIdx.x;
    if (idx >= NV * HDP / 2) return;
    int row = idx / (HDP / 2), j = (idx - row * (HDP / 2)) * 2;
    float2 v = (j < HD) ? *(const float2*)&emb[row * HD + j] : make_float2(0.f, 0.f);
    *(uint32_t*)&ef[row * HDP + j] = pack2h(v);
}

__global__ void mleaf_k(const float* __restrict__ pz, const float* __restrict__ ph,
                        float* __restrict__ mlf, __half* __restrict__ mlff)
{
    int idx = blockIdx.x * blockDim.x + threadIdx.x;
    if (idx >= NV * HDP / 2) return;
    int row = idx / (HDP / 2), j = (idx - row * (HDP / 2)) * 2;
    float2 v = make_float2(0.f, 0.f);
    if (j < HD) {
        int s = row * HD + j;
        float2 a = *(const float2*)&pz[s];
        float2 b = *(const float2*)&ph[s];
        v.x = tanhf(b.x) * sigf(a.x);
        v.y = tanhf(b.y) * sigf(a.y);
        *(float2*)&mlf[s] = v;
    }
    *(uint32_t*)&mlff[row * HDP + j] = pack2h(v);
}

// s/arm for node 15 (single child: leaf node 31)
__global__ void s0_k(const int* __restrict__ wid,
                     const float* __restrict__ pr, const float* __restrict__ rur,
                     const float* __restrict__ mlf,
                     __half* __restrict__ sf, __half* __restrict__ af)
{
    int idx = blockIdx.x * blockDim.x + threadIdx.x;
    if (idx >= NB * (HDP / 2)) return;
    int t = idx / (HDP / 2), j = (idx - t * (HDP / 2)) * 2;
    float2 s = make_float2(0.f, 0.f), a = s;
    if (j < HD) {
        int w15 = wid[t * NTREE + 15];
        int w31 = wid[t * NTREE + 31];
        s = *(const float2*)&mlf[w31 * HD + j];
        float2 ru = *(const float2*)&rur[w31 * HD + j];
        float2 pv = *(const float2*)&pr[w15 * HD + j];
        a = make_float2(sigf(pv.x + ru.x) * s.x, sigf(pv.y + ru.y) * s.y);
    }
    int d = t * HDP + j;
    *(uint32_t*)&sf[d] = pack2h(s);
    *(uint32_t*)&af[d] = pack2h(a);
}

// prep: m_new for children of parents [PLO,PLO+PCNT), emit m fp32 + mdf fp16 + parent s
template<int PLO, int PCNT, int CLO, int CCNT, int WMD>
__global__ void prep_k(const int* __restrict__ wid,
                       const float* __restrict__ pz, const float* __restrict__ ph,
                       const float* __restrict__ zp, const float* __restrict__ hp,
                       const float* __restrict__ mlf,
                       float* __restrict__ m, __half* __restrict__ mdf,
                       __half* __restrict__ sf)
{
    int idx = blockIdx.x * blockDim.x + threadIdx.x;
    if (idx >= NB * PCNT * (HDP / 2)) return;
    int row = idx / (HDP / 2), j = (idx - row * (HDP / 2)) * 2;
    int t = row / PCNT;
    int p = PLO + (row - t * PCNT);
    float2 msum = make_float2(0.f, 0.f);
    if (j < HD) {
#pragma unroll
        for (int ch = 0; ch < 2; ch++) {
            int c = 2 * p + 1 + ch;
            float2 mc;
            if (c >= 16) {
                int w = wid[t * NTREE + c];
                mc = *(const float2*)&mlf[w * HD + j];
            } else {
                int crow = t * CCNT + (c - CLO);
                int w = wid[t * NTREE + c];
                float2 pzv = *(const float2*)&pz[w * HD + j];
                float2 phv = *(const float2*)&ph[w * HD + j];
                float2 zpv = *(const float2*)&zp[crow * HD + j];
                float2 hpv = *(const float2*)&hp[crow * HD + j];
                int gc1 = 2 * c + 1, gc2 = 2 * c + 2;
                float2 s;
                if (gc1 < 16)  s = *(const float2*)&m[(t * NTREE + gc1) * HD + j];
                else           s = *(const float2*)&mlf[wid[t * NTREE + gc1] * HD + j];
                if (gc2 < NTREE) {
                    float2 s2;
                    if (gc2 < 16) s2 = *(const float2*)&m[(t * NTREE + gc2) * HD + j];
                    else          s2 = *(const float2*)&mlf[wid[t * NTREE + gc2] * HD + j];
                    s.x += s2.x; s.y += s2.y;
                }
                float zx = sigf(pzv.x + zpv.x);
                float zy = sigf(pzv.y + zpv.y);
                mc.x = (1.f - zx) * s.x + zx * tanhf(phv.x + hpv.x);
                mc.y = (1.f - zy) * s.y + zy * tanhf(phv.y + hpv.y);
                *(float2*)&m[(t * NTREE + c) * HD + j] = mc;
                if (WMD)
                    *(uint32_t*)&mdf[crow * HDP + j] = pack2h(mc);
            }
            msum.x += mc.x; msum.y += mc.y;
        }
    } else if (WMD) {
#pragma unroll
        for (int ch = 0; ch < 2; ch++) {
            int c = 2 * p + 1 + ch;
            if (c < 16) {
                int crow = t * CCNT + (c - CLO);
                *(uint32_t*)&mdf[crow * HDP + j] = 0;
            }
        }
    }
    *(uint32_t*)&sf[row * HDP + j] = pack2h(msum);
}

// arm for nodes [LO,LO+CNT): sum children rm (leaf rm from tables)
template<int LO, int CNT>
__global__ void armsplit_k(const int* __restrict__ wid,
                           const float* __restrict__ pr, const float* __restrict__ rur,
                           const float* __restrict__ mlf, const float* __restrict__ rm,
                           __half* __restrict__ af)
{
    int idx = blockIdx.x * blockDim.x + threadIdx.x;
    if (idx >= NB * CNT * (HDP / 2)) return;
    int row = idx / (HDP / 2), j = (idx - row * (HDP / 2)) * 2;
    int t = row / CNT;
    int n = LO + (row - t * CNT);
    float2 a = make_float2(0.f, 0.f);
    if (j < HD) {
        int wp = wid[t * NTREE + n];
#pragma unroll
        for (int ch = 0; ch < 2; ch++) {
            int c = 2 * n + 1 + ch;
            if (c < 16) {
                float2 rv = *(const float2*)&rm[(t * NTREE + c) * HD + j];
                a.x += rv.x; a.y += rv.y;
            } else {
                int w = wid[t * NTREE + c];
                float2 ru = *(const float2*)&rur[w * HD + j];
                float2 pv = *(const float2*)&pr[wp * HD + j];
                float2 mv = *(const float2*)&mlf[w * HD + j];
                a.x += sigf(pv.x + ru.x) * mv.x;
                a.y += sigf(pv.y + ru.y) * mv.y;
            }
        }
    }
    *(uint32_t*)&af[row * HDP + j] = pack2h(a);
}

// ================= launch =================
extern "C" void kernel_launch(void* const* d_in, const int* in_sizes, int n_in,
                              void* d_out, int out_size)
{
    const int*   wid = (const int*)  d_in[0];
    const float* emb = (const float*)d_in[1];
    const float* Wz  = (const float*)d_in[2];
    const float* bz  = (const float*)d_in[3];
    const float* Wr  = (const float*)d_in[4];
    const float* Ur  = (const float*)d_in[5];
    const float* bU  = (const float*)d_in[6];
    const float* Wh  = (const float*)d_in[7];
    const float* bh  = (const float*)d_in[8];
    const float* Wg  = (const float*)d_in[9];
    const float* bg  = (const float*)d_in[10];
    float* out = (float*)d_out;

    float *pz, *ph, *pr, *pgt, *mlf, *rur, *m, *rm, *zp, *hp;
    __half *ef, *mlff, *sf, *af, *mdf, *wh, *wl;
    cudaGetSymbolAddress((void**)&pz,  g_pz);
    cudaGetSymbolAddress((void**)&ph,  g_ph);
    cudaGetSymbolAddress((void**)&pr,  g_pr);
    cudaGetSymbolAddress((void**)&pgt, g_pgt);
    cudaGetSymbolAddress((void**)&mlf, g_mlf);
    cudaGetSymbolAddress((void**)&rur, g_rur);
    cudaGetSymbolAddress((void**)&m,   g_m);
    cudaGetSymbolAddress((void**)&rm,  g_rm);
    cudaGetSymbolAddress((void**)&zp,  g_zp);
    cudaGetSymbolAddress((void**)&hp,  g_hp);
    cudaGetSymbolAddress((void**)&ef,  g_ef);
    cudaGetSymbolAddress((void**)&mlff, g_mlff);
    cudaGetSymbolAddress((void**)&sf,  g_sf);
    cudaGetSymbolAddress((void**)&af,  g_af);
    cudaGetSymbolAddress((void**)&mdf, g_mdf);
    cudaGetSymbolAddress((void**)&wh,  g_wh);
    cudaGetSymbolAddress((void**)&wl,  g_wl);

    cudaFuncSetAttribute(tc_vocab, cudaFuncAttributeMaxDynamicSharedMemorySize, SMEMB);
    cudaFuncSetAttribute(tc_rur,   cudaFuncAttributeMaxDynamicSharedMemorySize, SMEMB);
    cudaFuncSetAttribute(tc_zh,    cudaFuncAttributeMaxDynamicSharedMemorySize, SMEMB);
    cudaFuncSetAttribute(tc_ur,    cudaFuncAttributeMaxDynamicSharedMemorySize, SMEMB);
    cudaFuncSetAttribute(tc_fin,   cudaFuncAttributeMaxDynamicSharedMemorySize, SMEMB);

    const int NX = (HD + BN - 1) / BN;   // 8
    auto yb = [](int M) { return (M + BM - 1) / BM; };
    auto gb = [](int n) { return (n + 255) / 256; };

    // prelude
    preconv_k<<<gb(8 * HD * HDP / 2), 256>>>(Wz, Wh, Wr, Ur, Wg, wh, wl);
    esplit_k<<<gb(NV * HDP / 2), 256>>>(emb, ef);
    tc_vocab<<<dim3(NX, yb(NV), 4), 256, SMEMB>>>(ef, wh, wl,
                                                  bz, bh, bU, bg, pz, ph, pr, pgt);
    mleaf_k<<<gb(NV * HDP / 2), 256>>>(pz, ph, mlf, mlff);
    tc_rur<<<dim3(NX, yb(NV)), 256, SMEMB>>>(mlff, wh, wl, rur);

    // level 0 (node 15)
    s0_k<<<gb(NB * HDP / 2), 256>>>(wid, pr, rur, mlf, sf, af);
    tc_zh<<<dim3(NX, yb(NB), 2), 256, SMEMB>>>(sf, af, wh, wl, zp, hp, NB);
    // L1: parents 7..14, interior child level {15}
    prep_k<7, 8, 15, 1, 1><<<gb(NB * 8 * HDP / 2), 256>>>(wid, pz, ph, zp, hp, mlf,
                                                          m, mdf, sf);
    tc_ur<<<dim3(NX, yb(NB)), 256, SMEMB>>>(mdf, wh, wl, rm, NB, 15, 0, wid, pr, m);
    armsplit_k<7, 8><<<gb(NB * 8 * HDP / 2), 256>>>(wid, pr, rur, mlf, rm, af);
    tc_zh<<<dim3(NX, yb(NB * 8), 2), 256, SMEMB>>>(sf, af, wh, wl, zp, hp, NB * 8);
    // L2: parents 3..6, children 7..14
    prep_k<3, 4, 7, 8, 1><<<gb(NB * 4 * HDP / 2), 256>>>(wid, pz, ph, zp, hp, mlf,
                                                         m, mdf, sf);
    tc_ur<<<dim3(NX, yb(NB * 8)), 256, SMEMB>>>(mdf, wh, wl, rm, NB * 8, 7, 3, wid, pr, m);
    armsplit_k<3, 4><<<gb(NB * 4 * HDP / 2), 256>>>(wid, pr, rur, mlf, rm, af);
    tc_zh<<<dim3(NX, yb(NB * 4), 2), 256, SMEMB>>>(sf, af, wh, wl, zp, hp, NB * 4);
    // L3: parents 1..2, children 3..6
    prep_k<1, 2, 3, 4, 1><<<gb(NB * 2 * HDP / 2), 256>>>(wid, pz, ph, zp, hp, mlf,
                                                         m, mdf, sf);
    tc_ur<<<dim3(NX, yb(NB * 4)), 256, SMEMB>>>(mdf, wh, wl, rm, NB * 4, 3, 2, wid, pr, m);
    armsplit_k<1, 2><<<gb(NB * 2 * HDP / 2), 256>>>(wid, pr, rur, mlf, rm, af);
    tc_zh<<<dim3(NX, yb(NB * 2), 2), 256, SMEMB>>>(sf, af, wh, wl, zp, hp, NB * 2);
    // root: parent 0, children 1..2 -> s_root
    prep_k<0, 1, 1, 2, 0><<<gb(NB * HDP / 2), 256>>>(wid, pz, ph, zp, hp, mlf,
                                                     m, mdf, sf);
    tc_fin<<<dim3(NX, yb(NB)), 256, SMEMB>>>(sf, wh, wl, out, wid, pgt);
}